// round 13
// baseline (speedup 1.0000x reference)
#include <cuda_runtime.h>
#include <cuda_fp16.h>
#include <math.h>
#include <stdint.h>

// ---------------- problem constants ----------------
#define BATCH 2
#define SEQ   4096
#define DM    768
#define DI    1536
#define NH    24
#define HD    64
#define DS    128
#define CHK   32
#define NC    128
#define CONV_DIM 1792
#define DPROJ 3352
#define DT_OFF 3328
#define ROWS  (BATCH*SEQ)
#define EPS   1e-6f

#define N1PAD 3456            // in_proj N padded to 27*128

// ---------------- scratch ----------------
__device__ __half g_y_h[(size_t)ROWS*DM];
__device__ __half g_y_l[(size_t)ROWS*DM];
__device__ __half g_winT[(size_t)N1PAD*DM];
__device__ __half g_woutT[(size_t)DM*DI];
__device__ __half g_yv_h[(size_t)ROWS*DI];
__device__ __half g_yv_l[(size_t)ROWS*DI];
__device__ float g_zx[(size_t)ROWS*DPROJ];
__device__ float g_xbc[(size_t)ROWS*CONV_DIM];
__device__ float g_dt[(size_t)ROWS*NH];
__device__ __half g_states[(size_t)BATCH*NC*NH*HD*DS];  // per-chunk states (fp16)
__device__ __half g_prev[(size_t)BATCH*NC*NH*HD*DS];    // scanned prefix (fp16)
__device__ float g_cd[BATCH*NC*NH];
__device__ float g_cb[(size_t)BATCH*NC*CHK*CHK];        // head-invariant C.B^T
__device__ float g_out[(size_t)ROWS*DM];

// ---------------- PTX helpers ----------------
__device__ __forceinline__ uint32_t smem_u32(const void* p) {
    uint32_t a;
    asm("{ .reg .u64 t; cvta.to.shared.u64 t, %1; cvt.u32.u64 %0, t; }" : "=r"(a) : "l"(p));
    return a;
}
#define CP16(dst, src)      asm volatile("cp.async.cg.shared.global [%0], [%1], 16;" :: "r"(dst), "l"(src))
#define CP_COMMIT()         asm volatile("cp.async.commit_group;" ::: "memory")
#define CP_WAIT1()          asm volatile("cp.async.wait_group 1;" ::: "memory")
#define CP_WAIT0()          asm volatile("cp.async.wait_group 0;" ::: "memory")

#define LDM4(r0, r1, r2, r3, addr) \
    asm volatile("ldmatrix.sync.aligned.m8n8.x4.shared.b16 {%0,%1,%2,%3}, [%4];" \
        : "=r"(r0), "=r"(r1), "=r"(r2), "=r"(r3) : "r"(addr))

#define MMA16816(c, a, b) \
    asm volatile("mma.sync.aligned.m16n8k16.row.col.f32.f16.f16.f32 " \
        "{%0,%1,%2,%3}, {%4,%5,%6,%7}, {%8,%9}, {%0,%1,%2,%3};" \
        : "+f"((c)[0]), "+f"((c)[1]), "+f"((c)[2]), "+f"((c)[3]) \
        : "r"((a)[0]), "r"((a)[1]), "r"((a)[2]), "r"((a)[3]), \
          "r"((b)[0]), "r"((b)[1]))

__device__ __forceinline__ void split2(float v, __half& h, __half& l) {
    h = __float2half_rn(v);
    l = __float2half_rn(v - __half2float(h));
}
__device__ __forceinline__ float siluf(float x) { return x / (1.f + expf(-x)); }

__device__ __forceinline__ float block_reduce_sum(float v) {
    __shared__ float sh[8];
    int lane = threadIdx.x & 31, w = threadIdx.x >> 5;
#pragma unroll
    for (int o = 16; o; o >>= 1) v += __shfl_down_sync(0xffffffffu, v, o);
    if (lane == 0) sh[w] = v;
    __syncthreads();
    if (w == 0) {
        v = (lane < 8) ? sh[lane] : 0.f;
#pragma unroll
        for (int o = 4; o; o >>= 1) v += __shfl_down_sync(0xffffffffu, v, o);
        if (lane == 0) sh[0] = v;
    }
    __syncthreads();
    return sh[0];
}

// ---------------- 1) pre-RMSNorm -> fp16 hi/lo ----------------
__global__ void __launch_bounds__(256) k_rms_pre(const float* __restrict__ x,
                                                 const float* __restrict__ sc) {
    int row = blockIdx.x, t = threadIdx.x;
    const float* xr = x + (size_t)row * DM;
    float v0 = xr[t], v1 = xr[t + 256], v2 = xr[t + 512];
    float ss = block_reduce_sum(v0 * v0 + v1 * v1 + v2 * v2);
    float inv = rsqrtf(ss * (1.0f / DM) + EPS);
    __half* yh = g_y_h + (size_t)row * DM;
    __half* yl = g_y_l + (size_t)row * DM;
    float y0 = v0 * inv * (1.f + sc[t]);
    float y1 = v1 * inv * (1.f + sc[t + 256]);
    float y2 = v2 * inv * (1.f + sc[t + 512]);
    split2(y0, yh[t], yl[t]);
    split2(y1, yh[t + 256], yl[t + 256]);
    split2(y2, yh[t + 512], yl[t + 512]);
}

// ---------------- weight transpose -> fp16 ----------------
__global__ void __launch_bounds__(256) k_wsplit(const float* __restrict__ W,
                                                __half* __restrict__ T,
                                                int Kin, int Nin, int Npad) {
    __shared__ float tile[32][33];
    int tx = threadIdx.x & 31, ty = threadIdx.x >> 5;
    int n0 = blockIdx.x * 32, k0 = blockIdx.y * 32;
#pragma unroll
    for (int i = 0; i < 4; i++) {
        int k = k0 + ty + i * 8, n = n0 + tx;
        tile[ty + i * 8][tx] = (k < Kin && n < Nin) ? W[(size_t)k * Nin + n] : 0.f;
    }
    __syncthreads();
#pragma unroll
    for (int i = 0; i < 4; i++) {
        int n = n0 + ty + i * 8, k = k0 + tx;
        if (n < Npad && k < Kin)
            T[(size_t)n * Kin + k] = __float2half_rn(tile[tx][ty + i * 8]);
    }
}

// ---------------- fp16-split GEMM via mma.sync: C[M,Nc] = A[M,K] * B^T -------
// A hi/lo fp16 (128-row M-tile); B single fp16 (NT-row N-tile).
// K-chunk 32, 3-stage cp.async, 2 MMAs per tile. Row stride 80B.
template <int K, int NT>
__global__ void __launch_bounds__(256, 2) k_gemm_mma(const __half* __restrict__ Ah,
                                                     const __half* __restrict__ Al,
                                                     const __half* __restrict__ B,
                                                     float* __restrict__ C, int Nc) {
    constexpr int NS = K / 32;
    constexpr int A_TILE = 128 * 80;          // 10240
    constexpr int B_TILE = NT * 80;
    constexpr int STAGE = 2 * A_TILE + B_TILE;
    constexpr int WM = (NT == 128) ? 2 : 4;   // warps along M
    constexpr int WMS = 128 / WM;             // warp M span: 64 or 32
    constexpr int MT = WMS / 16;              // m-frags: 4 or 2
    extern __shared__ char smem[];
    const uint32_t sb = smem_u32(smem);
    const int tid = threadIdx.x;
    const int wid = tid >> 5, lane = tid & 31;
    const int warp_m = wid % WM, warp_n = wid / WM;
    const int row0 = blockIdx.y * 128;
    const int n0   = blockIdx.x * NT;

    const __half* srcA[2] = { Ah + (size_t)row0 * K, Al + (size_t)row0 * K };
    const __half* srcB = B + (size_t)n0 * K;

    auto load_stage = [&](int s) {
        uint32_t base = sb + (uint32_t)(s % 3) * STAGE;
        int k0 = s * 32;
#pragma unroll
        for (int it = 0; it < 4; it++) {              // A hi/lo: 1024 cp ops
            int idx = it * 256 + tid;
            int tile = idx >> 9, rem = idx & 511;
            int r = rem >> 2, cs = rem & 3;
            CP16(base + (uint32_t)tile * A_TILE + (uint32_t)(r * 80 + cs * 16),
                 srcA[tile] + (size_t)r * K + k0 + cs * 8);
        }
#pragma unroll
        for (int it = 0; it < NT / 64; it++) {        // B: NT*4 cp ops
            int idx = it * 256 + tid;
            int r = idx >> 2, cs = idx & 3;
            CP16(base + 2 * A_TILE + (uint32_t)(r * 80 + cs * 16),
                 srcB + (size_t)r * K + k0 + cs * 8);
        }
        CP_COMMIT();
    };

    load_stage(0);
    load_stage(1);

    float acc[MT][4][4];
#pragma unroll
    for (int i = 0; i < MT; i++)
#pragma unroll
        for (int j = 0; j < 4; j++)
#pragma unroll
            for (int q = 0; q < 4; q++) acc[i][j][q] = 0.f;

    // per-lane ldmatrix offsets (elements); row stride 40 elements (80B)
    const int a_r = (lane & 7) + ((lane >> 3) & 1) * 8;
    const int a_c = ((lane >> 4) & 1) * 8;
    const int b_n = (lane & 7) + ((lane >> 4) & 1) * 8;
    const int b_k = ((lane >> 3) & 1) * 8;

    for (int s = 0; s < NS; s++) {
        if (s < NS - 1) { CP_WAIT1(); } else { CP_WAIT0(); }
        __syncthreads();
        if (s + 2 < NS) load_stage(s + 2);   // buffer (s-1)%3, drained before this sync
        uint32_t base = sb + (uint32_t)(s % 3) * STAGE;
#pragma unroll
        for (int kc = 0; kc < 2; kc++) {
            uint32_t bh[4][2];
#pragma unroll
            for (int pair = 0; pair < 2; pair++) {
                uint32_t boff = (uint32_t)(((warp_n * 32 + pair * 16 + b_n) * 40 + kc * 16 + b_k) * 2);
                uint32_t r0, r1, r2, r3;
                LDM4(r0, r1, r2, r3, base + 2 * A_TILE + boff);
                bh[pair * 2][0] = r0; bh[pair * 2][1] = r1;
                bh[pair * 2 + 1][0] = r2; bh[pair * 2 + 1][1] = r3;
            }
#pragma unroll
            for (int mt = 0; mt < MT; mt++) {
                uint32_t aoff = (uint32_t)(((warp_m * WMS + mt * 16 + a_r) * 40 + kc * 16 + a_c) * 2);
                uint32_t ah[4], al[4];
                LDM4(ah[0], ah[1], ah[2], ah[3], base + aoff);
                LDM4(al[0], al[1], al[2], al[3], base + A_TILE + aoff);
#pragma unroll
                for (int nt = 0; nt < 4; nt++) {
                    MMA16816(acc[mt][nt], ah, bh[nt]);
                    MMA16816(acc[mt][nt], al, bh[nt]);
                }
            }
        }
    }

    // epilogue: direct float2 stores
    const int g = lane >> 2, tg = lane & 3;
#pragma unroll
    for (int mt = 0; mt < MT; mt++) {
#pragma unroll
        for (int nt = 0; nt < 4; nt++) {
            int col = n0 + warp_n * 32 + nt * 8 + tg * 2;
            if (col < Nc) {
                int r = row0 + warp_m * WMS + mt * 16 + g;
                *(float2*)&C[(size_t)r * Nc + col] = make_float2(acc[mt][nt][0], acc[mt][nt][1]);
                *(float2*)&C[(size_t)(r + 8) * Nc + col] = make_float2(acc[mt][nt][2], acc[mt][nt][3]);
            }
        }
    }
}

#define SMEM_G1 (3 * (2 * 10240 + 128 * 80))   // 92160
#define SMEM_G2 (3 * (2 * 10240 + 64 * 80))    // 76800

// ---------------- 3) depthwise conv + SiLU + RoPE + dt softplus ----------------
__global__ void __launch_bounds__(256) k_conv(const float* __restrict__ conv_w,
                                              const float* __restrict__ conv_b,
                                              const float* __restrict__ dt_bias) {
    const int row = blockIdx.x;
    const int l = row & (SEQ - 1);
    const int b = row >> 12;
    const int t = threadIdx.x;
    __shared__ float s[CONV_DIM];

    for (int ch = t; ch < CONV_DIM; ch += 256) {
        float acc = conv_b[ch];
#pragma unroll
        for (int i = 0; i < 4; i++) {
            int ls = l + i - 3;
            if (ls >= 0)
                acc += g_zx[(size_t)(b * SEQ + ls) * DPROJ + DI + ch] * conv_w[ch * 4 + i];
        }
        s[ch] = siluf(acc);
    }
    __syncthreads();

    float r1 = 0.f, r2 = 0.f;
    int jb = 0;
    if (t < 64) {
        int which = t >> 5;
        int j = t & 31;
        jb = DI + which * DS + j;
        float freq = powf(10000.f, -(float)j / 32.f);
        float ang = (float)l * freq;
        float sn, cs;
        sincosf(ang, &sn, &cs);
        float v1 = s[jb], v2 = s[jb + 32];
        r1 = v1 * cs - v2 * sn;
        r2 = v1 * sn + v2 * cs;
    }
    __syncthreads();
    if (t < 64) { s[jb] = r1; s[jb + 32] = r2; }
    __syncthreads();

    float* dst = g_xbc + (size_t)row * CONV_DIM;
    for (int ch = t; ch < CONV_DIM; ch += 256) dst[ch] = s[ch];

    if (t < NH) {
        float v = g_zx[(size_t)row * DPROJ + DT_OFF + t] + dt_bias[t];
        g_dt[(size_t)row * NH + t] = (v > 20.f) ? v : log1pf(expf(v));
    }
}

// ---------------- 3.5) head-invariant CB[i][j] = C_i . B_j per chunk ----------
__global__ void __launch_bounds__(256) k_cb() {
    const int cb = blockIdx.x;          // b*NC + c
    const int t = threadIdx.x;
    __shared__ float Bs[32][129];
    __shared__ float Cs[32][129];
    const int row0 = cb * CHK;

    for (int idx = t; idx < 32 * 128; idx += 256) {
        int i = idx >> 7, n = idx & 127;
        size_t g = (size_t)(row0 + i) * CONV_DIM;
        Bs[i][n] = g_xbc[g + DI + n];
        Cs[i][n] = g_xbc[g + DI + DS + n];
    }
    __syncthreads();

    int i = t >> 3, j0 = (t & 7) << 2;
    float s0 = 0, s1 = 0, s2 = 0, s3 = 0;
    for (int n = 0; n < 128; n++) {
        float cv = Cs[i][n];
        s0 += cv * Bs[j0 + 0][n];
        s1 += cv * Bs[j0 + 1][n];
        s2 += cv * Bs[j0 + 2][n];
        s3 += cv * Bs[j0 + 3][n];
    }
    float* dst = g_cb + (size_t)cb * (CHK * CHK) + i * CHK + j0;
    dst[0] = s0; dst[1] = s1; dst[2] = s2; dst[3] = s3;
}

// ---------------- 4) states only: states[p][n] + chunk decay -------------------
__global__ void __launch_bounds__(256) k_states(const float* __restrict__ A_log) {
    const int h = blockIdx.x, c = blockIdx.y, b = blockIdx.z;
    __shared__ float XsT[64][36];
    __shared__ float dts[32], dacs[32], coeff[32];
    const int t = threadIdx.x;
    const int row0 = b * SEQ + c * CHK;

    for (int idx = t; idx < 32 * 64; idx += 256) {
        int i = idx >> 6, p = idx & 63;
        XsT[p][i] = g_xbc[(size_t)(row0 + i) * CONV_DIM + h * HD + p];
    }
    if (t < 32) dts[t] = g_dt[(size_t)(row0 + t) * NH + h];
    __syncthreads();
    if (t == 0) {
        float A = -expf(A_log[h]);
        float cs = 0.f;
        for (int i = 0; i < 32; i++) { cs += dts[i] * A; dacs[i] = cs; }
    }
    __syncthreads();
    if (t < 32) coeff[t] = dts[t] * expf(dacs[31] - dacs[t]);
    __syncthreads();

    {
        int n = t & 127;
        int pb2 = t >> 7;
        float Bv[32];
#pragma unroll
        for (int l = 0; l < 32; l++)
            Bv[l] = g_xbc[(size_t)(row0 + l) * CONV_DIM + DI + n] * coeff[l];
        size_t sb = ((size_t)((b * NC + c) * NH + h)) * (HD * DS);
        for (int e = 0; e < 32; e++) {
            int p = pb2 + 2 * e;
            float s = 0.f;
#pragma unroll
            for (int k = 0; k < 8; k++) {
                float4 x = *(const float4*)&XsT[p][k * 4];
                s += Bv[k * 4 + 0] * x.x;
                s += Bv[k * 4 + 1] * x.y;
                s += Bv[k * 4 + 2] * x.z;
                s += Bv[k * 4 + 3] * x.w;
            }
            g_states[sb + (size_t)p * DS + n] = __float2half_rn(s);
        }
    }
    if (t == 0) g_cd[(b * NC + c) * NH + h] = expf(dacs[31]);
}

// ---------------- 5) inter-chunk scan: states -> prev (fp16 storage) ----------
__global__ void __launch_bounds__(256) k_scan(const __half* __restrict__ st,
                                              __half* __restrict__ pv,
                                              const float* __restrict__ cd) {
    const int bh = blockIdx.x >> 3;
    const int j  = blockIdx.x & 7;
    const int b = bh / NH, h = bh % NH;
    const int elem = j * 1024 + threadIdx.x * 4;
    float s0 = 0.f, s1 = 0.f, s2 = 0.f, s3 = 0.f;
    for (int c = 0; c < NC; c++) {
        size_t base = ((size_t)((b * NC + c) * NH + h)) * (HD * DS) + elem;
        float cdv = cd[(b * NC + c) * NH + h];
        __half2 t01 = *(const __half2*)(st + base);
        __half2 t23 = *(const __half2*)(st + base + 2);
        __half2 p01 = __floats2half2_rn(s0, s1);
        __half2 p23 = __floats2half2_rn(s2, s3);
        *(__half2*)(pv + base) = p01;
        *(__half2*)(pv + base + 2) = p23;
        float2 f01 = __half22float2(t01);
        float2 f23 = __half22float2(t23);
        s0 = s0 * cdv + f01.x;
        s1 = s1 * cdv + f01.y;
        s2 = s2 * cdv + f23.x;
        s3 = s3 * cdv + f23.y;
    }
}

// ---------------- 6) merged Y: Yd + Yo + D*xin, gate -> yv fp16 hi/lo ----------
__global__ void __launch_bounds__(256) k_y(const float* __restrict__ A_log,
                                           const float* __restrict__ Dp) {
    const int h = blockIdx.x, c = blockIdx.y, b = blockIdx.z;
    __shared__ float Xs[32][68];
    __shared__ float Cs[32][129];
    __shared__ float PsT[64][68];
    __shared__ float att[32][33];
    __shared__ float dts[32], dacs[32];
    const int t = threadIdx.x;
    const int row0 = b * SEQ + c * CHK;
    const int cbi = b * NC + c;

    for (int idx = t; idx < 32 * 128; idx += 256) {
        int i = idx >> 7, n = idx & 127;
        Cs[i][n] = g_xbc[(size_t)(row0 + i) * CONV_DIM + DI + DS + n];
    }
    for (int idx = t; idx < 32 * 64; idx += 256) {
        int i = idx >> 6, p = idx & 63;
        Xs[i][p] = g_xbc[(size_t)(row0 + i) * CONV_DIM + h * HD + p];
    }
    if (t < 32) dts[t] = g_dt[(size_t)(row0 + t) * NH + h];
    __syncthreads();
    if (t == 0) {
        float A = -expf(A_log[h]);
        float cs = 0.f;
        for (int i = 0; i < 32; i++) { cs += dts[i] * A; dacs[i] = cs; }
    }
    __syncthreads();

    // att[i][j] = CB[i][j] * exp(dacs_i - dacs_j) * dt_j for j<=i
    {
        const float* cbp = g_cb + (size_t)cbi * (CHK * CHK);
        for (int idx = t; idx < 1024; idx += 256) {
            int i = idx >> 5, j = idx & 31;
            att[i][j] = (j <= i) ? cbp[idx] * expf(dacs[i] - dacs[j]) * dts[j] : 0.f;
        }
    }
    __syncthreads();

    const int i = t >> 3, p0 = (t & 7) << 3;

    // Yd
    float accd[8] = {0, 0, 0, 0, 0, 0, 0, 0};
    for (int j = 0; j <= i; j++) {
        float a = att[i][j];
        float4 x0 = *(const float4*)&Xs[j][p0];
        float4 x1 = *(const float4*)&Xs[j][p0 + 4];
        accd[0] += a * x0.x; accd[1] += a * x0.y;
        accd[2] += a * x0.z; accd[3] += a * x0.w;
        accd[4] += a * x1.x; accd[5] += a * x1.y;
        accd[6] += a * x1.z; accd[7] += a * x1.w;
    }

    // Yo
    float acc[8] = {0, 0, 0, 0, 0, 0, 0, 0};
    size_t pb = ((size_t)(cbi * NH + h)) * (HD * DS);
    for (int half = 0; half < 2; half++) {
        __syncthreads();
        for (int idx = t; idx < 64 * 64; idx += 256) {
            int p = idx >> 6, n = idx & 63;
            PsT[n][p] = __half2float(g_prev[pb + (size_t)p * DS + half * 64 + n]);
        }
        __syncthreads();
        for (int n = 0; n < 64; n++) {
            float cv = Cs[i][half * 64 + n];
            float4 a = *(const float4*)&PsT[n][p0];
            float4 bb = *(const float4*)&PsT[n][p0 + 4];
            acc[0] += cv * a.x;  acc[1] += cv * a.y;
            acc[2] += cv * a.z;  acc[3] += cv * a.w;
            acc[4] += cv * bb.x; acc[5] += cv * bb.y;
            acc[6] += cv * bb.z; acc[7] += cv * bb.w;
        }
    }
    float ei = expf(dacs[i]);
    float dph = Dp[h];
    size_t row = row0 + i;
#pragma unroll
    for (int q = 0; q < 8; q++) {
        int p = p0 + q;
        float xin = Xs[i][p];
        float z = g_zx[row * DPROJ + h * HD + p];
        size_t yi = row * DI + h * HD + p;
        float Y = accd[q] + ei * acc[q] + dph * xin;
        float outv = Y * siluf(z);
        split2(outv, g_yv_h[yi], g_yv_l[yi]);
    }
}

// ---------------- 8) post-RMSNorm + residual ----------------
__global__ void __launch_bounds__(256) k_final(const float* __restrict__ x,
                                               const float* __restrict__ sc,
                                               float* __restrict__ out) {
    int row = blockIdx.x, t = threadIdx.x;
    const float* gr = g_out + (size_t)row * DM;
    float v0 = gr[t], v1 = gr[t + 256], v2 = gr[t + 512];
    float ss = block_reduce_sum(v0 * v0 + v1 * v1 + v2 * v2);
    float inv = rsqrtf(ss * (1.0f / DM) + EPS);
    const float* xr = x + (size_t)row * DM;
    size_t o = (size_t)row * DM;
    out[o + t]       = xr[t]       + v0 * inv * (1.f + sc[t]);
    out[o + t + 256] = xr[t + 256] + v1 * inv * (1.f + sc[t + 256]);
    out[o + t + 512] = xr[t + 512] + v2 * inv * (1.f + sc[t + 512]);
}

// ---------------- launch -----------------------------------------------------
extern "C" void kernel_launch(void* const* d_in, const int* in_sizes, int n_in,
                              void* d_out, int out_size) {
    const float* x          = (const float*)d_in[0];
    const float* pre_scale  = (const float*)d_in[1];
    const float* post_scale = (const float*)d_in[2];
    const float* W_in       = (const float*)d_in[3];
    const float* conv_w     = (const float*)d_in[4];
    const float* conv_b     = (const float*)d_in[5];
    const float* dt_bias    = (const float*)d_in[6];
    const float* A_log      = (const float*)d_in[7];
    const float* D_param    = (const float*)d_in[8];
    const float* W_out      = (const float*)d_in[9];
    float* out = (float*)d_out;

    static int configured = 0;
    if (!configured) {
        cudaFuncSetAttribute((const void*)k_gemm_mma<768, 128>,
                             cudaFuncAttributeMaxDynamicSharedMemorySize, SMEM_G1);
        cudaFuncSetAttribute((const void*)k_gemm_mma<1536, 64>,
                             cudaFuncAttributeMaxDynamicSharedMemorySize, SMEM_G2);
        configured = 1;
    }

    __half *yh, *yl, *winT, *woutT, *yvh, *yvl, *stp, *pvp;
    float *zx, *outp, *cdp;
    cudaGetSymbolAddress((void**)&yh, g_y_h);
    cudaGetSymbolAddress((void**)&yl, g_y_l);
    cudaGetSymbolAddress((void**)&winT, g_winT);
    cudaGetSymbolAddress((void**)&woutT, g_woutT);
    cudaGetSymbolAddress((void**)&yvh, g_yv_h);
    cudaGetSymbolAddress((void**)&yvl, g_yv_l);
    cudaGetSymbolAddress((void**)&zx, g_zx);
    cudaGetSymbolAddress((void**)&outp, g_out);
    cudaGetSymbolAddress((void**)&stp, g_states);
    cudaGetSymbolAddress((void**)&pvp, g_prev);
    cudaGetSymbolAddress((void**)&cdp, g_cd);

    // launch index 3 == k_gemm_mma<768,128> (stable profiler reference)
    k_rms_pre<<<ROWS, 256>>>(x, pre_scale);
    k_wsplit<<<dim3(N1PAD / 32, DM / 32), 256>>>(W_in, winT, DM, DPROJ, N1PAD);
    k_wsplit<<<dim3(DM / 32, DI / 32), 256>>>(W_out, woutT, DI, DM, DM);
    k_gemm_mma<768, 128><<<dim3(N1PAD / 128, ROWS / 128), 256, SMEM_G1>>>(yh, yl, winT, zx, DPROJ);
    k_conv<<<ROWS, 256>>>(conv_w, conv_b, dt_bias);
    k_cb<<<BATCH * NC, 256>>>();
    k_states<<<dim3(NH, NC, BATCH), 256>>>(A_log);
    k_scan<<<BATCH * NH * 8, 256>>>(stp, pvp, cdp);
    k_y<<<dim3(NH, NC, BATCH), 256>>>(A_log, D_param);
    k_gemm_mma<1536, 64><<<dim3(DM / 64, ROWS / 128), 256, SMEM_G2>>>(yvh, yvl, woutT, outp, DM);
    k_final<<<ROWS, 256>>>(x, post_scale, out);
}

// round 14
// speedup vs baseline: 1.3468x; 1.3468x over previous
#include <cuda_runtime.h>
#include <cuda_fp16.h>
#include <math.h>
#include <stdint.h>

// ---------------- problem constants ----------------
#define BATCH 2
#define SEQ   4096
#define DM    768
#define DI    1536
#define NH    24
#define HD    64
#define DS    128
#define CHK   32
#define NC    128
#define CONV_DIM 1792
#define DPROJ 3352
#define DT_OFF 3328
#define ROWS  (BATCH*SEQ)
#define EPS   1e-6f

#define N1PAD 3456            // in_proj N padded to 27*128

// ---------------- scratch ----------------
__device__ __half g_y_h[(size_t)ROWS*DM];
__device__ __half g_y_l[(size_t)ROWS*DM];
__device__ __half g_winT[(size_t)N1PAD*DM];
__device__ __half g_woutT[(size_t)DM*DI];
__device__ __half g_yv_h[(size_t)ROWS*DI];
__device__ __half g_yv_l[(size_t)ROWS*DI];
__device__ float g_zx[(size_t)ROWS*DPROJ];
__device__ float g_xbc[(size_t)ROWS*CONV_DIM];
__device__ float g_dt[(size_t)ROWS*NH];
__device__ __half g_states[(size_t)BATCH*NC*NH*HD*DS];  // per-chunk states (fp16)
__device__ __half g_prev[(size_t)BATCH*NC*NH*HD*DS];    // scanned prefix (fp16)
__device__ float g_cd[BATCH*NC*NH];
__device__ float g_cb[(size_t)BATCH*NC*CHK*CHK];        // head-invariant C.B^T
__device__ float g_yv[(size_t)ROWS*DI];                 // Yd intermediate
__device__ float g_out[(size_t)ROWS*DM];

// ---------------- PTX helpers ----------------
__device__ __forceinline__ uint32_t smem_u32(const void* p) {
    uint32_t a;
    asm("{ .reg .u64 t; cvta.to.shared.u64 t, %1; cvt.u32.u64 %0, t; }" : "=r"(a) : "l"(p));
    return a;
}
#define CP16(dst, src)      asm volatile("cp.async.cg.shared.global [%0], [%1], 16;" :: "r"(dst), "l"(src))
#define CP_COMMIT()         asm volatile("cp.async.commit_group;" ::: "memory")
#define CP_WAIT1()          asm volatile("cp.async.wait_group 1;" ::: "memory")
#define CP_WAIT0()          asm volatile("cp.async.wait_group 0;" ::: "memory")

#define LDM4(r0, r1, r2, r3, addr) \
    asm volatile("ldmatrix.sync.aligned.m8n8.x4.shared.b16 {%0,%1,%2,%3}, [%4];" \
        : "=r"(r0), "=r"(r1), "=r"(r2), "=r"(r3) : "r"(addr))

#define MMA16816(c, a, b) \
    asm volatile("mma.sync.aligned.m16n8k16.row.col.f32.f16.f16.f32 " \
        "{%0,%1,%2,%3}, {%4,%5,%6,%7}, {%8,%9}, {%0,%1,%2,%3};" \
        : "+f"((c)[0]), "+f"((c)[1]), "+f"((c)[2]), "+f"((c)[3]) \
        : "r"((a)[0]), "r"((a)[1]), "r"((a)[2]), "r"((a)[3]), \
          "r"((b)[0]), "r"((b)[1]))

__device__ __forceinline__ void split2(float v, __half& h, __half& l) {
    h = __float2half_rn(v);
    l = __float2half_rn(v - __half2float(h));
}
__device__ __forceinline__ float siluf(float x) { return x / (1.f + expf(-x)); }

__device__ __forceinline__ float block_reduce_sum(float v) {
    __shared__ float sh[8];
    int lane = threadIdx.x & 31, w = threadIdx.x >> 5;
#pragma unroll
    for (int o = 16; o; o >>= 1) v += __shfl_down_sync(0xffffffffu, v, o);
    if (lane == 0) sh[w] = v;
    __syncthreads();
    if (w == 0) {
        v = (lane < 8) ? sh[lane] : 0.f;
#pragma unroll
        for (int o = 4; o; o >>= 1) v += __shfl_down_sync(0xffffffffu, v, o);
        if (lane == 0) sh[0] = v;
    }
    __syncthreads();
    return sh[0];
}

// ---------------- 1) pre-RMSNorm -> fp16 hi/lo ----------------
__global__ void __launch_bounds__(256) k_rms_pre(const float* __restrict__ x,
                                                 const float* __restrict__ sc) {
    int row = blockIdx.x, t = threadIdx.x;
    const float* xr = x + (size_t)row * DM;
    float v0 = xr[t], v1 = xr[t + 256], v2 = xr[t + 512];
    float ss = block_reduce_sum(v0 * v0 + v1 * v1 + v2 * v2);
    float inv = rsqrtf(ss * (1.0f / DM) + EPS);
    __half* yh = g_y_h + (size_t)row * DM;
    __half* yl = g_y_l + (size_t)row * DM;
    float y0 = v0 * inv * (1.f + sc[t]);
    float y1 = v1 * inv * (1.f + sc[t + 256]);
    float y2 = v2 * inv * (1.f + sc[t + 512]);
    split2(y0, yh[t], yl[t]);
    split2(y1, yh[t + 256], yl[t + 256]);
    split2(y2, yh[t + 512], yl[t + 512]);
}

// ---------------- weight transpose -> fp16 ----------------
__global__ void __launch_bounds__(256) k_wsplit(const float* __restrict__ W,
                                                __half* __restrict__ T,
                                                int Kin, int Nin, int Npad) {
    __shared__ float tile[32][33];
    int tx = threadIdx.x & 31, ty = threadIdx.x >> 5;
    int n0 = blockIdx.x * 32, k0 = blockIdx.y * 32;
#pragma unroll
    for (int i = 0; i < 4; i++) {
        int k = k0 + ty + i * 8, n = n0 + tx;
        tile[ty + i * 8][tx] = (k < Kin && n < Nin) ? W[(size_t)k * Nin + n] : 0.f;
    }
    __syncthreads();
#pragma unroll
    for (int i = 0; i < 4; i++) {
        int n = n0 + ty + i * 8, k = k0 + tx;
        if (n < Npad && k < Kin)
            T[(size_t)n * Kin + k] = __float2half_rn(tile[tx][ty + i * 8]);
    }
}

// ---------------- fp16-split GEMM via mma.sync: C[M,Nc] = A[M,K] * B^T -------
template <int K, int NT>
__global__ void __launch_bounds__(256, 2) k_gemm_mma(const __half* __restrict__ Ah,
                                                     const __half* __restrict__ Al,
                                                     const __half* __restrict__ B,
                                                     float* __restrict__ C, int Nc) {
    constexpr int NS = K / 32;
    constexpr int A_TILE = 128 * 80;          // 10240
    constexpr int B_TILE = NT * 80;
    constexpr int STAGE = 2 * A_TILE + B_TILE;
    constexpr int WM = (NT == 128) ? 2 : 4;
    constexpr int WMS = 128 / WM;
    constexpr int MT = WMS / 16;
    extern __shared__ char smem[];
    const uint32_t sb = smem_u32(smem);
    const int tid = threadIdx.x;
    const int wid = tid >> 5, lane = tid & 31;
    const int warp_m = wid % WM, warp_n = wid / WM;
    const int row0 = blockIdx.y * 128;
    const int n0   = blockIdx.x * NT;

    const __half* srcA[2] = { Ah + (size_t)row0 * K, Al + (size_t)row0 * K };
    const __half* srcB = B + (size_t)n0 * K;

    auto load_stage = [&](int s) {
        uint32_t base = sb + (uint32_t)(s % 3) * STAGE;
        int k0 = s * 32;
#pragma unroll
        for (int it = 0; it < 4; it++) {
            int idx = it * 256 + tid;
            int tile = idx >> 9, rem = idx & 511;
            int r = rem >> 2, cs = rem & 3;
            CP16(base + (uint32_t)tile * A_TILE + (uint32_t)(r * 80 + cs * 16),
                 srcA[tile] + (size_t)r * K + k0 + cs * 8);
        }
#pragma unroll
        for (int it = 0; it < NT / 64; it++) {
            int idx = it * 256 + tid;
            int r = idx >> 2, cs = idx & 3;
            CP16(base + 2 * A_TILE + (uint32_t)(r * 80 + cs * 16),
                 srcB + (size_t)r * K + k0 + cs * 8);
        }
        CP_COMMIT();
    };

    load_stage(0);
    load_stage(1);

    float acc[MT][4][4];
#pragma unroll
    for (int i = 0; i < MT; i++)
#pragma unroll
        for (int j = 0; j < 4; j++)
#pragma unroll
            for (int q = 0; q < 4; q++) acc[i][j][q] = 0.f;

    const int a_r = (lane & 7) + ((lane >> 3) & 1) * 8;
    const int a_c = ((lane >> 4) & 1) * 8;
    const int b_n = (lane & 7) + ((lane >> 4) & 1) * 8;
    const int b_k = ((lane >> 3) & 1) * 8;

    for (int s = 0; s < NS; s++) {
        if (s < NS - 1) { CP_WAIT1(); } else { CP_WAIT0(); }
        __syncthreads();
        if (s + 2 < NS) load_stage(s + 2);
        uint32_t base = sb + (uint32_t)(s % 3) * STAGE;
#pragma unroll
        for (int kc = 0; kc < 2; kc++) {
            uint32_t bh[4][2];
#pragma unroll
            for (int pair = 0; pair < 2; pair++) {
                uint32_t boff = (uint32_t)(((warp_n * 32 + pair * 16 + b_n) * 40 + kc * 16 + b_k) * 2);
                uint32_t r0, r1, r2, r3;
                LDM4(r0, r1, r2, r3, base + 2 * A_TILE + boff);
                bh[pair * 2][0] = r0; bh[pair * 2][1] = r1;
                bh[pair * 2 + 1][0] = r2; bh[pair * 2 + 1][1] = r3;
            }
#pragma unroll
            for (int mt = 0; mt < MT; mt++) {
                uint32_t aoff = (uint32_t)(((warp_m * WMS + mt * 16 + a_r) * 40 + kc * 16 + a_c) * 2);
                uint32_t ah[4], al[4];
                LDM4(ah[0], ah[1], ah[2], ah[3], base + aoff);
                LDM4(al[0], al[1], al[2], al[3], base + A_TILE + aoff);
#pragma unroll
                for (int nt = 0; nt < 4; nt++) {
                    MMA16816(acc[mt][nt], ah, bh[nt]);
                    MMA16816(acc[mt][nt], al, bh[nt]);
                }
            }
        }
    }

    const int g = lane >> 2, tg = lane & 3;
#pragma unroll
    for (int mt = 0; mt < MT; mt++) {
#pragma unroll
        for (int nt = 0; nt < 4; nt++) {
            int col = n0 + warp_n * 32 + nt * 8 + tg * 2;
            if (col < Nc) {
                int r = row0 + warp_m * WMS + mt * 16 + g;
                *(float2*)&C[(size_t)r * Nc + col] = make_float2(acc[mt][nt][0], acc[mt][nt][1]);
                *(float2*)&C[(size_t)(r + 8) * Nc + col] = make_float2(acc[mt][nt][2], acc[mt][nt][3]);
            }
        }
    }
}

#define SMEM_G1 (3 * (2 * 10240 + 128 * 80))   // 92160
#define SMEM_G2 (3 * (2 * 10240 + 64 * 80))    // 76800

// ---------------- 3) depthwise conv + SiLU + RoPE + dt softplus ----------------
__global__ void __launch_bounds__(256) k_conv(const float* __restrict__ conv_w,
                                              const float* __restrict__ conv_b,
                                              const float* __restrict__ dt_bias) {
    const int row = blockIdx.x;
    const int l = row & (SEQ - 1);
    const int b = row >> 12;
    const int t = threadIdx.x;
    __shared__ float s[CONV_DIM];

    for (int ch = t; ch < CONV_DIM; ch += 256) {
        float acc = conv_b[ch];
#pragma unroll
        for (int i = 0; i < 4; i++) {
            int ls = l + i - 3;
            if (ls >= 0)
                acc += g_zx[(size_t)(b * SEQ + ls) * DPROJ + DI + ch] * conv_w[ch * 4 + i];
        }
        s[ch] = siluf(acc);
    }
    __syncthreads();

    float r1 = 0.f, r2 = 0.f;
    int jb = 0;
    if (t < 64) {
        int which = t >> 5;
        int j = t & 31;
        jb = DI + which * DS + j;
        float freq = powf(10000.f, -(float)j / 32.f);
        float ang = (float)l * freq;
        float sn, cs;
        sincosf(ang, &sn, &cs);
        float v1 = s[jb], v2 = s[jb + 32];
        r1 = v1 * cs - v2 * sn;
        r2 = v1 * sn + v2 * cs;
    }
    __syncthreads();
    if (t < 64) { s[jb] = r1; s[jb + 32] = r2; }
    __syncthreads();

    float* dst = g_xbc + (size_t)row * CONV_DIM;
    for (int ch = t; ch < CONV_DIM; ch += 256) dst[ch] = s[ch];

    if (t < NH) {
        float v = g_zx[(size_t)row * DPROJ + DT_OFF + t] + dt_bias[t];
        g_dt[(size_t)row * NH + t] = (v > 20.f) ? v : log1pf(expf(v));
    }
}

// ---------------- 3.5) head-invariant CB[i][j] = C_i . B_j per chunk ----------
__global__ void __launch_bounds__(256) k_cb() {
    const int cb = blockIdx.x;
    const int t = threadIdx.x;
    __shared__ float Bs[32][129];
    __shared__ float Cs[32][129];
    const int row0 = cb * CHK;

    for (int idx = t; idx < 32 * 128; idx += 256) {
        int i = idx >> 7, n = idx & 127;
        size_t g = (size_t)(row0 + i) * CONV_DIM;
        Bs[i][n] = g_xbc[g + DI + n];
        Cs[i][n] = g_xbc[g + DI + DS + n];
    }
    __syncthreads();

    int i = t >> 3, j0 = (t & 7) << 2;
    float s0 = 0, s1 = 0, s2 = 0, s3 = 0;
    for (int n = 0; n < 128; n++) {
        float cv = Cs[i][n];
        s0 += cv * Bs[j0 + 0][n];
        s1 += cv * Bs[j0 + 1][n];
        s2 += cv * Bs[j0 + 2][n];
        s3 += cv * Bs[j0 + 3][n];
    }
    float* dst = g_cb + (size_t)cb * (CHK * CHK) + i * CHK + j0;
    dst[0] = s0; dst[1] = s1; dst[2] = s2; dst[3] = s3;
}

// ---------------- 4) intra-chunk: Yd + states (R12 version) -------------------
__global__ void __launch_bounds__(256) k_chunk(const float* __restrict__ A_log) {
    const int h = blockIdx.x, c = blockIdx.y, b = blockIdx.z;
    __shared__ float Xs[32][68];
    __shared__ float XsT[64][36];
    __shared__ float att[32][33];
    __shared__ float dts[32], dacs[32], coeff[32];
    const int t = threadIdx.x;
    const int row0 = b * SEQ + c * CHK;
    const int cb = b * NC + c;

    for (int idx = t; idx < 32 * 64; idx += 256) {
        int i = idx >> 6, p = idx & 63;
        float v = g_xbc[(size_t)(row0 + i) * CONV_DIM + h * HD + p];
        Xs[i][p] = v;
        XsT[p][i] = v;
    }
    if (t < 32) dts[t] = g_dt[(size_t)(row0 + t) * NH + h];
    __syncthreads();
    if (t == 0) {
        float A = -expf(A_log[h]);
        float cs = 0.f;
        for (int i = 0; i < 32; i++) { cs += dts[i] * A; dacs[i] = cs; }
    }
    __syncthreads();
    if (t < 32) coeff[t] = dts[t] * expf(dacs[31] - dacs[t]);

    {
        const float* cbp = g_cb + (size_t)cb * (CHK * CHK);
        for (int idx = t; idx < 1024; idx += 256) {
            int i = idx >> 5, j = idx & 31;
            att[i][j] = (j <= i) ? cbp[idx] * expf(dacs[i] - dacs[j]) * dts[j] : 0.f;
        }
    }
    __syncthreads();

    // Yd
    {
        int i = t >> 3, p0 = (t & 7) << 3;
        float acc[8] = {0, 0, 0, 0, 0, 0, 0, 0};
        for (int j = 0; j <= i; j++) {
            float a = att[i][j];
            float4 x0 = *(const float4*)&Xs[j][p0];
            float4 x1 = *(const float4*)&Xs[j][p0 + 4];
            acc[0] += a * x0.x; acc[1] += a * x0.y;
            acc[2] += a * x0.z; acc[3] += a * x0.w;
            acc[4] += a * x1.x; acc[5] += a * x1.y;
            acc[6] += a * x1.z; acc[7] += a * x1.w;
        }
        size_t g = (size_t)(row0 + i) * DI + h * HD + p0;
#pragma unroll
        for (int q = 0; q < 8; q++) g_yv[g + q] = acc[q];
    }

    // states
    {
        int n = t & 127;
        int pb2 = t >> 7;
        float Bv[32];
#pragma unroll
        for (int l = 0; l < 32; l++)
            Bv[l] = g_xbc[(size_t)(row0 + l) * CONV_DIM + DI + n] * coeff[l];
        size_t sb = ((size_t)((b * NC + c) * NH + h)) * (HD * DS);
        for (int e = 0; e < 32; e++) {
            int p = pb2 + 2 * e;
            float s = 0.f;
#pragma unroll
            for (int k = 0; k < 8; k++) {
                float4 x = *(const float4*)&XsT[p][k * 4];
                s += Bv[k * 4 + 0] * x.x;
                s += Bv[k * 4 + 1] * x.y;
                s += Bv[k * 4 + 2] * x.z;
                s += Bv[k * 4 + 3] * x.w;
            }
            g_states[sb + (size_t)p * DS + n] = __float2half_rn(s);
        }
    }
    if (t == 0) g_cd[(b * NC + c) * NH + h] = expf(dacs[31]);
}

// ---------------- 5) inter-chunk scan: states -> prev (fp16 storage) ----------
__global__ void __launch_bounds__(256) k_scan(const __half* __restrict__ st,
                                              __half* __restrict__ pv,
                                              const float* __restrict__ cd) {
    const int bh = blockIdx.x >> 3;
    const int j  = blockIdx.x & 7;
    const int b = bh / NH, h = bh % NH;
    const int elem = j * 1024 + threadIdx.x * 4;
    float s0 = 0.f, s1 = 0.f, s2 = 0.f, s3 = 0.f;
    for (int c = 0; c < NC; c++) {
        size_t base = ((size_t)((b * NC + c) * NH + h)) * (HD * DS) + elem;
        float cdv = cd[(b * NC + c) * NH + h];
        __half2 t01 = *(const __half2*)(st + base);
        __half2 t23 = *(const __half2*)(st + base + 2);
        __half2 p01 = __floats2half2_rn(s0, s1);
        __half2 p23 = __floats2half2_rn(s2, s3);
        *(__half2*)(pv + base) = p01;
        *(__half2*)(pv + base + 2) = p23;
        float2 f01 = __half22float2(t01);
        float2 f23 = __half22float2(t23);
        s0 = s0 * cdv + f01.x;
        s1 = s1 * cdv + f01.y;
        s2 = s2 * cdv + f23.x;
        s3 = s3 * cdv + f23.y;
    }
}

// ---------------- 6) Yo via tensor-core MMA + gate -> yv fp16 hi/lo -----------
// Yo[32x64] = C[32x128](hi/lo fp16) @ prev^T (prev fp16 [p][n], K-major n).
__global__ void __launch_bounds__(256) k_yo(const float* __restrict__ A_log,
                                            const float* __restrict__ Dp) {
    const int h = blockIdx.x, c = blockIdx.y, b = blockIdx.z;
    __shared__ __half Cs_h[32][136];
    __shared__ __half Cs_l[32][136];
    __shared__ __half Pv[64][136];
    __shared__ float Yo_s[32][68];
    __shared__ float dts[32], dacs[32];
    const int t = threadIdx.x;
    const int wid = t >> 5, lane = t & 31;
    const int row0 = b * SEQ + c * CHK;

    // stage C hi/lo
    for (int idx = t; idx < 32 * 128; idx += 256) {
        int i = idx >> 7, n = idx & 127;
        float v = g_xbc[(size_t)(row0 + i) * CONV_DIM + DI + DS + n];
        split2(v, Cs_h[i][n], Cs_l[i][n]);
    }
    // stage prev tile (fp16, 8B copies)
    {
        size_t pb = ((size_t)((b * NC + c) * NH + h)) * (HD * DS);
        const __half* src = g_prev + pb;
#pragma unroll
        for (int it = 0; it < 8; it++) {
            int idx = it * 256 + t;              // 0..2047
            int p = idx >> 5, n0 = (idx & 31) * 4;
            *(uint2*)&Pv[p][n0] = *(const uint2*)(src + (size_t)p * DS + n0);
        }
    }
    if (t < 32) dts[t] = g_dt[(size_t)(row0 + t) * NH + h];
    __syncthreads();
    if (t == 0) {
        float A = -expf(A_log[h]);
        float cs = 0.f;
        for (int i = 0; i < 32; i++) { cs += dts[i] * A; dacs[i] = cs; }
    }

    // MMA: 8 warps = (mw 0..1) x (nw 0..3 covering 16 p each), K=128 in 8 steps
    {
        const int mw = wid & 1, nw = wid >> 1;
        const int a_r = (lane & 7) + ((lane >> 3) & 1) * 8;
        const int a_c = ((lane >> 4) & 1) * 8;
        const int b_n = (lane & 7) + ((lane >> 4) & 1) * 8;
        const int b_k = ((lane >> 3) & 1) * 8;
        float acc0[4] = {0, 0, 0, 0}, acc1[4] = {0, 0, 0, 0};
        const uint32_t csh = smem_u32(Cs_h);
        const uint32_t csl = smem_u32(Cs_l);
        const uint32_t pvb = smem_u32(Pv);
#pragma unroll
        for (int k0 = 0; k0 < 128; k0 += 16) {
            uint32_t ah[4], al[4], bb0[2], bb1[2];
            uint32_t aoff = (uint32_t)(((mw * 16 + a_r) * 136 + k0 + a_c) * 2);
            LDM4(ah[0], ah[1], ah[2], ah[3], csh + aoff);
            LDM4(al[0], al[1], al[2], al[3], csl + aoff);
            uint32_t boff = (uint32_t)(((nw * 16 + b_n) * 136 + k0 + b_k) * 2);
            uint32_t r0, r1, r2, r3;
            LDM4(r0, r1, r2, r3, pvb + boff);
            bb0[0] = r0; bb0[1] = r1; bb1[0] = r2; bb1[1] = r3;
            MMA16816(acc0, ah, bb0);
            MMA16816(acc0, al, bb0);
            MMA16816(acc1, ah, bb1);
            MMA16816(acc1, al, bb1);
        }
        int g = lane >> 2, tg = lane & 3;
        int pc0 = nw * 16 + tg * 2;
        Yo_s[mw * 16 + g][pc0]         = acc0[0];
        Yo_s[mw * 16 + g][pc0 + 1]     = acc0[1];
        Yo_s[mw * 16 + g + 8][pc0]     = acc0[2];
        Yo_s[mw * 16 + g + 8][pc0 + 1] = acc0[3];
        Yo_s[mw * 16 + g][pc0 + 8]         = acc1[0];
        Yo_s[mw * 16 + g][pc0 + 9]         = acc1[1];
        Yo_s[mw * 16 + g + 8][pc0 + 8]     = acc1[2];
        Yo_s[mw * 16 + g + 8][pc0 + 9]     = acc1[3];
    }
    __syncthreads();

    // tail: combine with Yd (g_yv), D*xin, gate, split-store
    const int i = t >> 3, p0 = (t & 7) << 3;
    float ei = expf(dacs[i]);
    float dph = Dp[h];
    size_t row = row0 + i;
#pragma unroll
    for (int q = 0; q < 8; q++) {
        int p = p0 + q;
        float xin = g_xbc[row * CONV_DIM + h * HD + p];
        float z = g_zx[row * DPROJ + h * HD + p];
        size_t yi = row * DI + h * HD + p;
        float Y = g_yv[yi] + ei * Yo_s[i][p] + dph * xin;
        float outv = Y * siluf(z);
        split2(outv, g_yv_h[yi], g_yv_l[yi]);
    }
}

// ---------------- 8) post-RMSNorm + residual ----------------
__global__ void __launch_bounds__(256) k_final(const float* __restrict__ x,
                                               const float* __restrict__ sc,
                                               float* __restrict__ out) {
    int row = blockIdx.x, t = threadIdx.x;
    const float* gr = g_out + (size_t)row * DM;
    float v0 = gr[t], v1 = gr[t + 256], v2 = gr[t + 512];
    float ss = block_reduce_sum(v0 * v0 + v1 * v1 + v2 * v2);
    float inv = rsqrtf(ss * (1.0f / DM) + EPS);
    const float* xr = x + (size_t)row * DM;
    size_t o = (size_t)row * DM;
    out[o + t]       = xr[t]       + v0 * inv * (1.f + sc[t]);
    out[o + t + 256] = xr[t + 256] + v1 * inv * (1.f + sc[t + 256]);
    out[o + t + 512] = xr[t + 512] + v2 * inv * (1.f + sc[t + 512]);
}

// ---------------- launch -----------------------------------------------------
extern "C" void kernel_launch(void* const* d_in, const int* in_sizes, int n_in,
                              void* d_out, int out_size) {
    const float* x          = (const float*)d_in[0];
    const float* pre_scale  = (const float*)d_in[1];
    const float* post_scale = (const float*)d_in[2];
    const float* W_in       = (const float*)d_in[3];
    const float* conv_w     = (const float*)d_in[4];
    const float* conv_b     = (const float*)d_in[5];
    const float* dt_bias    = (const float*)d_in[6];
    const float* A_log      = (const float*)d_in[7];
    const float* D_param    = (const float*)d_in[8];
    const float* W_out      = (const float*)d_in[9];
    float* out = (float*)d_out;

    static int configured = 0;
    if (!configured) {
        cudaFuncSetAttribute((const void*)k_gemm_mma<768, 128>,
                             cudaFuncAttributeMaxDynamicSharedMemorySize, SMEM_G1);
        cudaFuncSetAttribute((const void*)k_gemm_mma<1536, 64>,
                             cudaFuncAttributeMaxDynamicSharedMemorySize, SMEM_G2);
        configured = 1;
    }

    __half *yh, *yl, *winT, *woutT, *yvh, *yvl, *stp, *pvp;
    float *zx, *outp, *cdp;
    cudaGetSymbolAddress((void**)&yh, g_y_h);
    cudaGetSymbolAddress((void**)&yl, g_y_l);
    cudaGetSymbolAddress((void**)&winT, g_winT);
    cudaGetSymbolAddress((void**)&woutT, g_woutT);
    cudaGetSymbolAddress((void**)&yvh, g_yv_h);
    cudaGetSymbolAddress((void**)&yvl, g_yv_l);
    cudaGetSymbolAddress((void**)&zx, g_zx);
    cudaGetSymbolAddress((void**)&outp, g_out);
    cudaGetSymbolAddress((void**)&stp, g_states);
    cudaGetSymbolAddress((void**)&pvp, g_prev);
    cudaGetSymbolAddress((void**)&cdp, g_cd);

    // launch index 3 == k_gemm_mma<768,128> (stable profiler reference)
    k_rms_pre<<<ROWS, 256>>>(x, pre_scale);
    k_wsplit<<<dim3(N1PAD / 32, DM / 32), 256>>>(W_in, winT, DM, DPROJ, N1PAD);
    k_wsplit<<<dim3(DM / 32, DI / 32), 256>>>(W_out, woutT, DI, DM, DM);
    k_gemm_mma<768, 128><<<dim3(N1PAD / 128, ROWS / 128), 256, SMEM_G1>>>(yh, yl, winT, zx, DPROJ);
    k_conv<<<ROWS, 256>>>(conv_w, conv_b, dt_bias);
    k_cb<<<BATCH * NC, 256>>>();
    k_chunk<<<dim3(NH, NC, BATCH), 256>>>(A_log);
    k_scan<<<BATCH * NH * 8, 256>>>(stp, pvp, cdp);
    k_yo<<<dim3(NH, NC, BATCH), 256>>>(A_log, D_param);
    k_gemm_mma<1536, 64><<<dim3(DM / 64, ROWS / 128), 256, SMEM_G2>>>(yvh, yvl, woutT, outp, DM);
    k_final<<<ROWS, 256>>>(x, post_scale, out);
}

// round 15
// speedup vs baseline: 1.3908x; 1.0327x over previous
#include <cuda_runtime.h>
#include <cuda_fp16.h>
#include <math.h>
#include <stdint.h>

// ---------------- problem constants ----------------
#define BATCH 2
#define SEQ   4096
#define DM    768
#define DI    1536
#define NH    24
#define HD    64
#define DS    128
#define CHK   32
#define NC    128
#define CONV_DIM 1792
#define DPROJ 3352
#define DT_OFF 3328
#define ROWS  (BATCH*SEQ)
#define EPS   1e-6f

#define N1PAD 3456            // in_proj N padded to 27*128

// ---------------- scratch ----------------
__device__ __half g_y_h[(size_t)ROWS*DM];
__device__ __half g_y_l[(size_t)ROWS*DM];
__device__ __half g_winT[(size_t)N1PAD*DM];
__device__ __half g_woutT[(size_t)DM*DI];
__device__ __half g_yv_h[(size_t)ROWS*DI];
__device__ __half g_yv_l[(size_t)ROWS*DI];
__device__ float g_zx[(size_t)ROWS*DPROJ];
__device__ float g_xbc[(size_t)ROWS*CONV_DIM];
__device__ float g_dt[(size_t)ROWS*NH];
__device__ __half g_states[(size_t)BATCH*NC*NH*HD*DS];  // per-chunk states (fp16)
__device__ __half g_prev[(size_t)BATCH*NC*NH*HD*DS];    // scanned prefix (fp16)
__device__ float g_cd[BATCH*NC*NH];
__device__ float g_cb[(size_t)BATCH*NC*CHK*CHK];        // head-invariant C.B^T
__device__ float g_yv[(size_t)ROWS*DI];                 // Yd intermediate
__device__ float g_out[(size_t)ROWS*DM];

// ---------------- PTX helpers ----------------
__device__ __forceinline__ uint32_t smem_u32(const void* p) {
    uint32_t a;
    asm("{ .reg .u64 t; cvta.to.shared.u64 t, %1; cvt.u32.u64 %0, t; }" : "=r"(a) : "l"(p));
    return a;
}
#define CP16(dst, src)      asm volatile("cp.async.cg.shared.global [%0], [%1], 16;" :: "r"(dst), "l"(src))
#define CP_COMMIT()         asm volatile("cp.async.commit_group;" ::: "memory")
#define CP_WAIT1()          asm volatile("cp.async.wait_group 1;" ::: "memory")
#define CP_WAIT0()          asm volatile("cp.async.wait_group 0;" ::: "memory")

#define LDM4(r0, r1, r2, r3, addr) \
    asm volatile("ldmatrix.sync.aligned.m8n8.x4.shared.b16 {%0,%1,%2,%3}, [%4];" \
        : "=r"(r0), "=r"(r1), "=r"(r2), "=r"(r3) : "r"(addr))

#define MMA16816(c, a, b) \
    asm volatile("mma.sync.aligned.m16n8k16.row.col.f32.f16.f16.f32 " \
        "{%0,%1,%2,%3}, {%4,%5,%6,%7}, {%8,%9}, {%0,%1,%2,%3};" \
        : "+f"((c)[0]), "+f"((c)[1]), "+f"((c)[2]), "+f"((c)[3]) \
        : "r"((a)[0]), "r"((a)[1]), "r"((a)[2]), "r"((a)[3]), \
          "r"((b)[0]), "r"((b)[1]))

__device__ __forceinline__ void split2(float v, __half& h, __half& l) {
    h = __float2half_rn(v);
    l = __float2half_rn(v - __half2float(h));
}
__device__ __forceinline__ float siluf(float x) { return x / (1.f + expf(-x)); }

__device__ __forceinline__ float block_reduce_sum(float v) {
    __shared__ float sh[8];
    int lane = threadIdx.x & 31, w = threadIdx.x >> 5;
#pragma unroll
    for (int o = 16; o; o >>= 1) v += __shfl_down_sync(0xffffffffu, v, o);
    if (lane == 0) sh[w] = v;
    __syncthreads();
    if (w == 0) {
        v = (lane < 8) ? sh[lane] : 0.f;
#pragma unroll
        for (int o = 4; o; o >>= 1) v += __shfl_down_sync(0xffffffffu, v, o);
        if (lane == 0) sh[0] = v;
    }
    __syncthreads();
    return sh[0];
}

// ---------------- 1) pre-RMSNorm -> fp16 hi/lo ----------------
__global__ void __launch_bounds__(256) k_rms_pre(const float* __restrict__ x,
                                                 const float* __restrict__ sc) {
    int row = blockIdx.x, t = threadIdx.x;
    const float* xr = x + (size_t)row * DM;
    float v0 = xr[t], v1 = xr[t + 256], v2 = xr[t + 512];
    float ss = block_reduce_sum(v0 * v0 + v1 * v1 + v2 * v2);
    float inv = rsqrtf(ss * (1.0f / DM) + EPS);
    __half* yh = g_y_h + (size_t)row * DM;
    __half* yl = g_y_l + (size_t)row * DM;
    float y0 = v0 * inv * (1.f + sc[t]);
    float y1 = v1 * inv * (1.f + sc[t + 256]);
    float y2 = v2 * inv * (1.f + sc[t + 512]);
    split2(y0, yh[t], yl[t]);
    split2(y1, yh[t + 256], yl[t + 256]);
    split2(y2, yh[t + 512], yl[t + 512]);
}

// ---------------- weight transpose -> fp16 ----------------
__global__ void __launch_bounds__(256) k_wsplit(const float* __restrict__ W,
                                                __half* __restrict__ T,
                                                int Kin, int Nin, int Npad) {
    __shared__ float tile[32][33];
    int tx = threadIdx.x & 31, ty = threadIdx.x >> 5;
    int n0 = blockIdx.x * 32, k0 = blockIdx.y * 32;
#pragma unroll
    for (int i = 0; i < 4; i++) {
        int k = k0 + ty + i * 8, n = n0 + tx;
        tile[ty + i * 8][tx] = (k < Kin && n < Nin) ? W[(size_t)k * Nin + n] : 0.f;
    }
    __syncthreads();
#pragma unroll
    for (int i = 0; i < 4; i++) {
        int n = n0 + ty + i * 8, k = k0 + tx;
        if (n < Npad && k < Kin)
            T[(size_t)n * Kin + k] = __float2half_rn(tile[tx][ty + i * 8]);
    }
}

// ---------------- fp16-split GEMM via mma.sync: C[M,Nc] = A[M,K] * B^T -------
template <int K, int NT>
__global__ void __launch_bounds__(256, 2) k_gemm_mma(const __half* __restrict__ Ah,
                                                     const __half* __restrict__ Al,
                                                     const __half* __restrict__ B,
                                                     float* __restrict__ C, int Nc) {
    constexpr int NS = K / 32;
    constexpr int A_TILE = 128 * 80;          // 10240
    constexpr int B_TILE = NT * 80;
    constexpr int STAGE = 2 * A_TILE + B_TILE;
    constexpr int WM = (NT == 128) ? 2 : 4;
    constexpr int WMS = 128 / WM;
    constexpr int MT = WMS / 16;
    extern __shared__ char smem[];
    const uint32_t sb = smem_u32(smem);
    const int tid = threadIdx.x;
    const int wid = tid >> 5, lane = tid & 31;
    const int warp_m = wid % WM, warp_n = wid / WM;
    const int row0 = blockIdx.y * 128;
    const int n0   = blockIdx.x * NT;

    const __half* srcA[2] = { Ah + (size_t)row0 * K, Al + (size_t)row0 * K };
    const __half* srcB = B + (size_t)n0 * K;

    auto load_stage = [&](int s) {
        uint32_t base = sb + (uint32_t)(s % 3) * STAGE;
        int k0 = s * 32;
#pragma unroll
        for (int it = 0; it < 4; it++) {
            int idx = it * 256 + tid;
            int tile = idx >> 9, rem = idx & 511;
            int r = rem >> 2, cs = rem & 3;
            CP16(base + (uint32_t)tile * A_TILE + (uint32_t)(r * 80 + cs * 16),
                 srcA[tile] + (size_t)r * K + k0 + cs * 8);
        }
#pragma unroll
        for (int it = 0; it < NT / 64; it++) {
            int idx = it * 256 + tid;
            int r = idx >> 2, cs = idx & 3;
            CP16(base + 2 * A_TILE + (uint32_t)(r * 80 + cs * 16),
                 srcB + (size_t)r * K + k0 + cs * 8);
        }
        CP_COMMIT();
    };

    load_stage(0);
    load_stage(1);

    float acc[MT][4][4];
#pragma unroll
    for (int i = 0; i < MT; i++)
#pragma unroll
        for (int j = 0; j < 4; j++)
#pragma unroll
            for (int q = 0; q < 4; q++) acc[i][j][q] = 0.f;

    const int a_r = (lane & 7) + ((lane >> 3) & 1) * 8;
    const int a_c = ((lane >> 4) & 1) * 8;
    const int b_n = (lane & 7) + ((lane >> 4) & 1) * 8;
    const int b_k = ((lane >> 3) & 1) * 8;

    for (int s = 0; s < NS; s++) {
        if (s < NS - 1) { CP_WAIT1(); } else { CP_WAIT0(); }
        __syncthreads();
        if (s + 2 < NS) load_stage(s + 2);
        uint32_t base = sb + (uint32_t)(s % 3) * STAGE;
#pragma unroll
        for (int kc = 0; kc < 2; kc++) {
            uint32_t bh[4][2];
#pragma unroll
            for (int pair = 0; pair < 2; pair++) {
                uint32_t boff = (uint32_t)(((warp_n * 32 + pair * 16 + b_n) * 40 + kc * 16 + b_k) * 2);
                uint32_t r0, r1, r2, r3;
                LDM4(r0, r1, r2, r3, base + 2 * A_TILE + boff);
                bh[pair * 2][0] = r0; bh[pair * 2][1] = r1;
                bh[pair * 2 + 1][0] = r2; bh[pair * 2 + 1][1] = r3;
            }
#pragma unroll
            for (int mt = 0; mt < MT; mt++) {
                uint32_t aoff = (uint32_t)(((warp_m * WMS + mt * 16 + a_r) * 40 + kc * 16 + a_c) * 2);
                uint32_t ah[4], al[4];
                LDM4(ah[0], ah[1], ah[2], ah[3], base + aoff);
                LDM4(al[0], al[1], al[2], al[3], base + A_TILE + aoff);
#pragma unroll
                for (int nt = 0; nt < 4; nt++) {
                    MMA16816(acc[mt][nt], ah, bh[nt]);
                    MMA16816(acc[mt][nt], al, bh[nt]);
                }
            }
        }
    }

    const int g = lane >> 2, tg = lane & 3;
#pragma unroll
    for (int mt = 0; mt < MT; mt++) {
#pragma unroll
        for (int nt = 0; nt < 4; nt++) {
            int col = n0 + warp_n * 32 + nt * 8 + tg * 2;
            if (col < Nc) {
                int r = row0 + warp_m * WMS + mt * 16 + g;
                *(float2*)&C[(size_t)r * Nc + col] = make_float2(acc[mt][nt][0], acc[mt][nt][1]);
                *(float2*)&C[(size_t)(r + 8) * Nc + col] = make_float2(acc[mt][nt][2], acc[mt][nt][3]);
            }
        }
    }
}

#define SMEM_G1 (3 * (2 * 10240 + 128 * 80))   // 92160
#define SMEM_G2 (3 * (2 * 10240 + 64 * 80))    // 76800

// ---------------- 3) depthwise conv + SiLU + RoPE + dt softplus ----------------
__global__ void __launch_bounds__(256) k_conv(const float* __restrict__ conv_w,
                                              const float* __restrict__ conv_b,
                                              const float* __restrict__ dt_bias) {
    const int row = blockIdx.x;
    const int l = row & (SEQ - 1);
    const int b = row >> 12;
    const int t = threadIdx.x;
    __shared__ float s[CONV_DIM];

    for (int ch = t; ch < CONV_DIM; ch += 256) {
        float acc = conv_b[ch];
#pragma unroll
        for (int i = 0; i < 4; i++) {
            int ls = l + i - 3;
            if (ls >= 0)
                acc += g_zx[(size_t)(b * SEQ + ls) * DPROJ + DI + ch] * conv_w[ch * 4 + i];
        }
        s[ch] = siluf(acc);
    }
    __syncthreads();

    float r1 = 0.f, r2 = 0.f;
    int jb = 0;
    if (t < 64) {
        int which = t >> 5;
        int j = t & 31;
        jb = DI + which * DS + j;
        float freq = powf(10000.f, -(float)j / 32.f);
        float ang = (float)l * freq;
        float sn, cs;
        sincosf(ang, &sn, &cs);
        float v1 = s[jb], v2 = s[jb + 32];
        r1 = v1 * cs - v2 * sn;
        r2 = v1 * sn + v2 * cs;
    }
    __syncthreads();
    if (t < 64) { s[jb] = r1; s[jb + 32] = r2; }
    __syncthreads();

    float* dst = g_xbc + (size_t)row * CONV_DIM;
    for (int ch = t; ch < CONV_DIM; ch += 256) dst[ch] = s[ch];

    if (t < NH) {
        float v = g_zx[(size_t)row * DPROJ + DT_OFF + t] + dt_bias[t];
        g_dt[(size_t)row * NH + t] = (v > 20.f) ? v : log1pf(expf(v));
    }
}

// ---------------- 3.5) head-invariant CB[i][j] = C_i . B_j per chunk ----------
__global__ void __launch_bounds__(256) k_cb() {
    const int cb = blockIdx.x;
    const int t = threadIdx.x;
    __shared__ float Bs[32][129];
    __shared__ float Cs[32][129];
    const int row0 = cb * CHK;

    for (int idx = t; idx < 32 * 128; idx += 256) {
        int i = idx >> 7, n = idx & 127;
        size_t g = (size_t)(row0 + i) * CONV_DIM;
        Bs[i][n] = g_xbc[g + DI + n];
        Cs[i][n] = g_xbc[g + DI + DS + n];
    }
    __syncthreads();

    int i = t >> 3, j0 = (t & 7) << 2;
    float s0 = 0, s1 = 0, s2 = 0, s3 = 0;
    for (int n = 0; n < 128; n++) {
        float cv = Cs[i][n];
        s0 += cv * Bs[j0 + 0][n];
        s1 += cv * Bs[j0 + 1][n];
        s2 += cv * Bs[j0 + 2][n];
        s3 += cv * Bs[j0 + 3][n];
    }
    float* dst = g_cb + (size_t)cb * (CHK * CHK) + i * CHK + j0;
    dst[0] = s0; dst[1] = s1; dst[2] = s2; dst[3] = s3;
}

// ---------------- 4) intra-chunk via tensor cores: Yd + states ----------------
// Yd[32x64]   = att[32x32](fp16) @ X[32x64]     (X hi/lo fp16)
// states[64p x 128n] = X^T[64x32](hi/lo) @ BcT  (Bc = coeff_l*B[l][n], fp16)
__global__ void __launch_bounds__(256) k_chunk(const float* __restrict__ A_log) {
    const int h = blockIdx.x, c = blockIdx.y, b = blockIdx.z;
    __shared__ __half XTh[64][40];
    __shared__ __half XTl[64][40];
    __shared__ __half attf[32][40];
    __shared__ __half BcT[128][40];
    __shared__ float dts[32], dacs[32], coeff[32];
    const int t = threadIdx.x;
    const int wid = t >> 5, lane = t & 31;
    const int row0 = b * SEQ + c * CHK;
    const int cb = b * NC + c;

    // stage X^T hi/lo: XT[p][l]
    for (int idx = t; idx < 32 * 64; idx += 256) {
        int i = idx >> 6, p = idx & 63;
        float v = g_xbc[(size_t)(row0 + i) * CONV_DIM + h * HD + p];
        split2(v, XTh[p][i], XTl[p][i]);
    }
    if (t < 32) dts[t] = g_dt[(size_t)(row0 + t) * NH + h];
    __syncthreads();
    if (t == 0) {
        float A = -expf(A_log[h]);
        float cs = 0.f;
        for (int i = 0; i < 32; i++) { cs += dts[i] * A; dacs[i] = cs; }
    }
    __syncthreads();
    if (t < 32) coeff[t] = dts[t] * expf(dacs[31] - dacs[t]);
    __syncthreads();

    // stage att (fp16) and BcT[n][l] = coeff_l * B[l][n] (fp16)
    {
        const float* cbp = g_cb + (size_t)cb * (CHK * CHK);
        for (int idx = t; idx < 1024; idx += 256) {
            int i = idx >> 5, j = idx & 31;
            float a = (j <= i) ? cbp[idx] * expf(dacs[i] - dacs[j]) * dts[j] : 0.f;
            attf[i][j] = __float2half_rn(a);
        }
    }
    for (int idx = t; idx < 32 * 128; idx += 256) {
        int l = idx >> 7, n = idx & 127;
        BcT[n][l] = __float2half_rn(g_xbc[(size_t)(row0 + l) * CONV_DIM + DI + n] * coeff[l]);
    }
    __syncthreads();

    const int a_r = (lane & 7) + ((lane >> 3) & 1) * 8;
    const int a_c = ((lane >> 4) & 1) * 8;
    const int b_n = (lane & 7) + ((lane >> 4) & 1) * 8;
    const int b_k = ((lane >> 3) & 1) * 8;
    const int g = lane >> 2, tg = lane & 3;
    const uint32_t xh = smem_u32(XTh), xl = smem_u32(XTl);
    const uint32_t atp = smem_u32(attf), bct = smem_u32(BcT);

    // --- Yd: 8 warps = (mw 0..1) x (nw 0..3 of 16 p) ---
    {
        const int mw = wid & 1, nw = wid >> 1;
        float acc0[4] = {0, 0, 0, 0}, acc1[4] = {0, 0, 0, 0};
#pragma unroll
        for (int k0 = 0; k0 < 32; k0 += 16) {
            uint32_t av[4], bh0[2], bh1[2], bl0[2], bl1[2];
            uint32_t aoff = (uint32_t)(((mw * 16 + a_r) * 40 + k0 + a_c) * 2);
            LDM4(av[0], av[1], av[2], av[3], atp + aoff);
            uint32_t boff = (uint32_t)(((nw * 16 + b_n) * 40 + k0 + b_k) * 2);
            uint32_t r0, r1, r2, r3;
            LDM4(r0, r1, r2, r3, xh + boff);
            bh0[0] = r0; bh0[1] = r1; bh1[0] = r2; bh1[1] = r3;
            LDM4(r0, r1, r2, r3, xl + boff);
            bl0[0] = r0; bl0[1] = r1; bl1[0] = r2; bl1[1] = r3;
            MMA16816(acc0, av, bh0);
            MMA16816(acc0, av, bl0);
            MMA16816(acc1, av, bh1);
            MMA16816(acc1, av, bl1);
        }
        int col0 = h * HD + nw * 16 + tg * 2;
        size_t r0 = (size_t)(row0 + mw * 16 + g) * DI;
        size_t r1 = (size_t)(row0 + mw * 16 + g + 8) * DI;
        *(float2*)&g_yv[r0 + col0]     = make_float2(acc0[0], acc0[1]);
        *(float2*)&g_yv[r1 + col0]     = make_float2(acc0[2], acc0[3]);
        *(float2*)&g_yv[r0 + col0 + 8] = make_float2(acc1[0], acc1[1]);
        *(float2*)&g_yv[r1 + col0 + 8] = make_float2(acc1[2], acc1[3]);
    }

    // --- states: 8 warps = (mw 0..3 of 16 p) x (nw 0..1 of 64 n) ---
    {
        const int mw = wid & 3, nw = wid >> 2;
        size_t sbase = ((size_t)((b * NC + c) * NH + h)) * (HD * DS);
#pragma unroll
        for (int ntile = 0; ntile < 4; ntile++) {
            float acc0[4] = {0, 0, 0, 0}, acc1[4] = {0, 0, 0, 0};
#pragma unroll
            for (int k0 = 0; k0 < 32; k0 += 16) {
                uint32_t ah[4], al[4], bb0[2], bb1[2];
                uint32_t aoff = (uint32_t)(((mw * 16 + a_r) * 40 + k0 + a_c) * 2);
                LDM4(ah[0], ah[1], ah[2], ah[3], xh + aoff);
                LDM4(al[0], al[1], al[2], al[3], xl + aoff);
                uint32_t boff = (uint32_t)(((nw * 64 + ntile * 16 + b_n) * 40 + k0 + b_k) * 2);
                uint32_t r0, r1, r2, r3;
                LDM4(r0, r1, r2, r3, bct + boff);
                bb0[0] = r0; bb0[1] = r1; bb1[0] = r2; bb1[1] = r3;
                MMA16816(acc0, ah, bb0);
                MMA16816(acc0, al, bb0);
                MMA16816(acc1, ah, bb1);
                MMA16816(acc1, al, bb1);
            }
            int p0 = mw * 16 + g;
            int n0 = nw * 64 + ntile * 16 + tg * 2;
            *(__half2*)&g_states[sbase + (size_t)p0 * DS + n0]           = __floats2half2_rn(acc0[0], acc0[1]);
            *(__half2*)&g_states[sbase + (size_t)(p0 + 8) * DS + n0]     = __floats2half2_rn(acc0[2], acc0[3]);
            *(__half2*)&g_states[sbase + (size_t)p0 * DS + n0 + 8]       = __floats2half2_rn(acc1[0], acc1[1]);
            *(__half2*)&g_states[sbase + (size_t)(p0 + 8) * DS + n0 + 8] = __floats2half2_rn(acc1[2], acc1[3]);
        }
    }
    if (t == 0) g_cd[(b * NC + c) * NH + h] = expf(dacs[31]);
}

// ---------------- 5) inter-chunk scan: states -> prev (fp16 storage) ----------
__global__ void __launch_bounds__(256) k_scan(const __half* __restrict__ st,
                                              __half* __restrict__ pv,
                                              const float* __restrict__ cd) {
    const int bh = blockIdx.x >> 3;
    const int j  = blockIdx.x & 7;
    const int b = bh / NH, h = bh % NH;
    const int elem = j * 1024 + threadIdx.x * 4;
    float s0 = 0.f, s1 = 0.f, s2 = 0.f, s3 = 0.f;
    for (int c = 0; c < NC; c++) {
        size_t base = ((size_t)((b * NC + c) * NH + h)) * (HD * DS) + elem;
        float cdv = cd[(b * NC + c) * NH + h];
        __half2 t01 = *(const __half2*)(st + base);
        __half2 t23 = *(const __half2*)(st + base + 2);
        __half2 p01 = __floats2half2_rn(s0, s1);
        __half2 p23 = __floats2half2_rn(s2, s3);
        *(__half2*)(pv + base) = p01;
        *(__half2*)(pv + base + 2) = p23;
        float2 f01 = __half22float2(t01);
        float2 f23 = __half22float2(t23);
        s0 = s0 * cdv + f01.x;
        s1 = s1 * cdv + f01.y;
        s2 = s2 * cdv + f23.x;
        s3 = s3 * cdv + f23.y;
    }
}

// ---------------- 6) Yo via tensor-core MMA + gate -> yv fp16 hi/lo -----------
__global__ void __launch_bounds__(256) k_yo(const float* __restrict__ A_log,
                                            const float* __restrict__ Dp) {
    const int h = blockIdx.x, c = blockIdx.y, b = blockIdx.z;
    __shared__ __half Cs_h[32][136];
    __shared__ __half Cs_l[32][136];
    __shared__ __half Pv[64][136];
    __shared__ float Yo_s[32][68];
    __shared__ float dts[32], dacs[32];
    const int t = threadIdx.x;
    const int wid = t >> 5, lane = t & 31;
    const int row0 = b * SEQ + c * CHK;

    for (int idx = t; idx < 32 * 128; idx += 256) {
        int i = idx >> 7, n = idx & 127;
        float v = g_xbc[(size_t)(row0 + i) * CONV_DIM + DI + DS + n];
        split2(v, Cs_h[i][n], Cs_l[i][n]);
    }
    {
        size_t pb = ((size_t)((b * NC + c) * NH + h)) * (HD * DS);
        const __half* src = g_prev + pb;
#pragma unroll
        for (int it = 0; it < 8; it++) {
            int idx = it * 256 + t;
            int p = idx >> 5, n0 = (idx & 31) * 4;
            *(uint2*)&Pv[p][n0] = *(const uint2*)(src + (size_t)p * DS + n0);
        }
    }
    if (t < 32) dts[t] = g_dt[(size_t)(row0 + t) * NH + h];
    __syncthreads();
    if (t == 0) {
        float A = -expf(A_log[h]);
        float cs = 0.f;
        for (int i = 0; i < 32; i++) { cs += dts[i] * A; dacs[i] = cs; }
    }

    {
        const int mw = wid & 1, nw = wid >> 1;
        const int a_r = (lane & 7) + ((lane >> 3) & 1) * 8;
        const int a_c = ((lane >> 4) & 1) * 8;
        const int b_n = (lane & 7) + ((lane >> 4) & 1) * 8;
        const int b_k = ((lane >> 3) & 1) * 8;
        float acc0[4] = {0, 0, 0, 0}, acc1[4] = {0, 0, 0, 0};
        const uint32_t csh = smem_u32(Cs_h);
        const uint32_t csl = smem_u32(Cs_l);
        const uint32_t pvb = smem_u32(Pv);
#pragma unroll
        for (int k0 = 0; k0 < 128; k0 += 16) {
            uint32_t ah[4], al[4], bb0[2], bb1[2];
            uint32_t aoff = (uint32_t)(((mw * 16 + a_r) * 136 + k0 + a_c) * 2);
            LDM4(ah[0], ah[1], ah[2], ah[3], csh + aoff);
            LDM4(al[0], al[1], al[2], al[3], csl + aoff);
            uint32_t boff = (uint32_t)(((nw * 16 + b_n) * 136 + k0 + b_k) * 2);
            uint32_t r0, r1, r2, r3;
            LDM4(r0, r1, r2, r3, pvb + boff);
            bb0[0] = r0; bb0[1] = r1; bb1[0] = r2; bb1[1] = r3;
            MMA16816(acc0, ah, bb0);
            MMA16816(acc0, al, bb0);
            MMA16816(acc1, ah, bb1);
            MMA16816(acc1, al, bb1);
        }
        int g = lane >> 2, tg = lane & 3;
        int pc0 = nw * 16 + tg * 2;
        Yo_s[mw * 16 + g][pc0]         = acc0[0];
        Yo_s[mw * 16 + g][pc0 + 1]     = acc0[1];
        Yo_s[mw * 16 + g + 8][pc0]     = acc0[2];
        Yo_s[mw * 16 + g + 8][pc0 + 1] = acc0[3];
        Yo_s[mw * 16 + g][pc0 + 8]         = acc1[0];
        Yo_s[mw * 16 + g][pc0 + 9]         = acc1[1];
        Yo_s[mw * 16 + g + 8][pc0 + 8]     = acc1[2];
        Yo_s[mw * 16 + g + 8][pc0 + 9]     = acc1[3];
    }
    __syncthreads();

    const int i = t >> 3, p0 = (t & 7) << 3;
    float ei = expf(dacs[i]);
    float dph = Dp[h];
    size_t row = row0 + i;
#pragma unroll
    for (int q = 0; q < 8; q++) {
        int p = p0 + q;
        float xin = g_xbc[row * CONV_DIM + h * HD + p];
        float z = g_zx[row * DPROJ + h * HD + p];
        size_t yi = row * DI + h * HD + p;
        float Y = g_yv[yi] + ei * Yo_s[i][p] + dph * xin;
        float outv = Y * siluf(z);
        split2(outv, g_yv_h[yi], g_yv_l[yi]);
    }
}

// ---------------- 8) post-RMSNorm + residual ----------------
__global__ void __launch_bounds__(256) k_final(const float* __restrict__ x,
                                               const float* __restrict__ sc,
                                               float* __restrict__ out) {
    int row = blockIdx.x, t = threadIdx.x;
    const float* gr = g_out + (size_t)row * DM;
    float v0 = gr[t], v1 = gr[t + 256], v2 = gr[t + 512];
    float ss = block_reduce_sum(v0 * v0 + v1 * v1 + v2 * v2);
    float inv = rsqrtf(ss * (1.0f / DM) + EPS);
    const float* xr = x + (size_t)row * DM;
    size_t o = (size_t)row * DM;
    out[o + t]       = xr[t]       + v0 * inv * (1.f + sc[t]);
    out[o + t + 256] = xr[t + 256] + v1 * inv * (1.f + sc[t + 256]);
    out[o + t + 512] = xr[t + 512] + v2 * inv * (1.f + sc[t + 512]);
}

// ---------------- launch -----------------------------------------------------
extern "C" void kernel_launch(void* const* d_in, const int* in_sizes, int n_in,
                              void* d_out, int out_size) {
    const float* x          = (const float*)d_in[0];
    const float* pre_scale  = (const float*)d_in[1];
    const float* post_scale = (const float*)d_in[2];
    const float* W_in       = (const float*)d_in[3];
    const float* conv_w     = (const float*)d_in[4];
    const float* conv_b     = (const float*)d_in[5];
    const float* dt_bias    = (const float*)d_in[6];
    const float* A_log      = (const float*)d_in[7];
    const float* D_param    = (const float*)d_in[8];
    const float* W_out      = (const float*)d_in[9];
    float* out = (float*)d_out;

    static int configured = 0;
    if (!configured) {
        cudaFuncSetAttribute((const void*)k_gemm_mma<768, 128>,
                             cudaFuncAttributeMaxDynamicSharedMemorySize, SMEM_G1);
        cudaFuncSetAttribute((const void*)k_gemm_mma<1536, 64>,
                             cudaFuncAttributeMaxDynamicSharedMemorySize, SMEM_G2);
        configured = 1;
    }

    __half *yh, *yl, *winT, *woutT, *yvh, *yvl, *stp, *pvp;
    float *zx, *outp, *cdp;
    cudaGetSymbolAddress((void**)&yh, g_y_h);
    cudaGetSymbolAddress((void**)&yl, g_y_l);
    cudaGetSymbolAddress((void**)&winT, g_winT);
    cudaGetSymbolAddress((void**)&woutT, g_woutT);
    cudaGetSymbolAddress((void**)&yvh, g_yv_h);
    cudaGetSymbolAddress((void**)&yvl, g_yv_l);
    cudaGetSymbolAddress((void**)&zx, g_zx);
    cudaGetSymbolAddress((void**)&outp, g_out);
    cudaGetSymbolAddress((void**)&stp, g_states);
    cudaGetSymbolAddress((void**)&pvp, g_prev);
    cudaGetSymbolAddress((void**)&cdp, g_cd);

    // launch index 3 == k_gemm_mma<768,128> (stable profiler reference)
    k_rms_pre<<<ROWS, 256>>>(x, pre_scale);
    k_wsplit<<<dim3(N1PAD / 32, DM / 32), 256>>>(W_in, winT, DM, DPROJ, N1PAD);
    k_wsplit<<<dim3(DM / 32, DI / 32), 256>>>(W_out, woutT, DI, DM, DM);
    k_gemm_mma<768, 128><<<dim3(N1PAD / 128, ROWS / 128), 256, SMEM_G1>>>(yh, yl, winT, zx, DPROJ);
    k_conv<<<ROWS, 256>>>(conv_w, conv_b, dt_bias);
    k_cb<<<BATCH * NC, 256>>>();
    k_chunk<<<dim3(NH, NC, BATCH), 256>>>(A_log);
    k_scan<<<BATCH * NH * 8, 256>>>(stp, pvp, cdp);
    k_yo<<<dim3(NH, NC, BATCH), 256>>>(A_log, D_param);
    k_gemm_mma<1536, 64><<<dim3(DM / 64, ROWS / 128), 256, SMEM_G2>>>(yvh, yvl, woutT, outp, DM);
    k_final<<<ROWS, 256>>>(x, post_scale, out);
}

// round 16
// speedup vs baseline: 1.8775x; 1.3499x over previous
#include <cuda_runtime.h>
#include <cuda_fp16.h>
#include <math.h>
#include <stdint.h>

// ---------------- problem constants ----------------
#define BATCH 2
#define SEQ   4096
#define DM    768
#define DI    1536
#define NH    24
#define HD    64
#define DS    128
#define CHK   32
#define NC    128
#define CONV_DIM 1792
#define DPROJ 3352
#define DT_OFF 3328
#define ROWS  (BATCH*SEQ)
#define EPS   1e-6f

#define N1PAD 3456            // in_proj N padded to 27*128

// ---------------- scratch ----------------
__device__ __half g_y_h[(size_t)ROWS*DM];
__device__ __half g_winT[(size_t)N1PAD*DM];
__device__ __half g_woutT[(size_t)DM*DI];
__device__ __half g_yv_h[(size_t)ROWS*DI];
__device__ float g_zx[(size_t)ROWS*DPROJ];
__device__ float g_xbc[(size_t)ROWS*CONV_DIM];
__device__ float g_dt[(size_t)ROWS*NH];
__device__ __half g_states[(size_t)BATCH*NC*NH*HD*DS];  // per-chunk states (fp16)
__device__ __half g_prev[(size_t)BATCH*NC*NH*HD*DS];    // scanned prefix (fp16)
__device__ float g_cd[BATCH*NC*NH];
__device__ float g_cb[(size_t)BATCH*NC*CHK*CHK];        // head-invariant C.B^T
__device__ float g_yv[(size_t)ROWS*DI];                 // Yd intermediate
__device__ float g_out[(size_t)ROWS*DM];

// ---------------- PTX helpers ----------------
__device__ __forceinline__ uint32_t smem_u32(const void* p) {
    uint32_t a;
    asm("{ .reg .u64 t; cvta.to.shared.u64 t, %1; cvt.u32.u64 %0, t; }" : "=r"(a) : "l"(p));
    return a;
}
#define CP16(dst, src)      asm volatile("cp.async.cg.shared.global [%0], [%1], 16;" :: "r"(dst), "l"(src))
#define CP_COMMIT()         asm volatile("cp.async.commit_group;" ::: "memory")
#define CP_WAIT1()          asm volatile("cp.async.wait_group 1;" ::: "memory")
#define CP_WAIT0()          asm volatile("cp.async.wait_group 0;" ::: "memory")

#define LDM4(r0, r1, r2, r3, addr) \
    asm volatile("ldmatrix.sync.aligned.m8n8.x4.shared.b16 {%0,%1,%2,%3}, [%4];" \
        : "=r"(r0), "=r"(r1), "=r"(r2), "=r"(r3) : "r"(addr))

#define MMA16816(c, a, b) \
    asm volatile("mma.sync.aligned.m16n8k16.row.col.f32.f16.f16.f32 " \
        "{%0,%1,%2,%3}, {%4,%5,%6,%7}, {%8,%9}, {%0,%1,%2,%3};" \
        : "+f"((c)[0]), "+f"((c)[1]), "+f"((c)[2]), "+f"((c)[3]) \
        : "r"((a)[0]), "r"((a)[1]), "r"((a)[2]), "r"((a)[3]), \
          "r"((b)[0]), "r"((b)[1]))

__device__ __forceinline__ void split2(float v, __half& h, __half& l) {
    h = __float2half_rn(v);
    l = __float2half_rn(v - __half2float(h));
}
__device__ __forceinline__ float siluf(float x) { return x / (1.f + expf(-x)); }

__device__ __forceinline__ float block_reduce_sum(float v) {
    __shared__ float sh[8];
    int lane = threadIdx.x & 31, w = threadIdx.x >> 5;
#pragma unroll
    for (int o = 16; o; o >>= 1) v += __shfl_down_sync(0xffffffffu, v, o);
    if (lane == 0) sh[w] = v;
    __syncthreads();
    if (w == 0) {
        v = (lane < 8) ? sh[lane] : 0.f;
#pragma unroll
        for (int o = 4; o; o >>= 1) v += __shfl_down_sync(0xffffffffu, v, o);
        if (lane == 0) sh[0] = v;
    }
    __syncthreads();
    return sh[0];
}

// ---------------- 1) pre-RMSNorm -> fp16 ----------------
__global__ void __launch_bounds__(256) k_rms_pre(const float* __restrict__ x,
                                                 const float* __restrict__ sc) {
    int row = blockIdx.x, t = threadIdx.x;
    const float* xr = x + (size_t)row * DM;
    float v0 = xr[t], v1 = xr[t + 256], v2 = xr[t + 512];
    float ss = block_reduce_sum(v0 * v0 + v1 * v1 + v2 * v2);
    float inv = rsqrtf(ss * (1.0f / DM) + EPS);
    __half* yh = g_y_h + (size_t)row * DM;
    yh[t]       = __float2half_rn(v0 * inv * (1.f + sc[t]));
    yh[t + 256] = __float2half_rn(v1 * inv * (1.f + sc[t + 256]));
    yh[t + 512] = __float2half_rn(v2 * inv * (1.f + sc[t + 512]));
}

// ---------------- weight transpose -> fp16 ----------------
__global__ void __launch_bounds__(256) k_wsplit(const float* __restrict__ W,
                                                __half* __restrict__ T,
                                                int Kin, int Nin, int Npad) {
    __shared__ float tile[32][33];
    int tx = threadIdx.x & 31, ty = threadIdx.x >> 5;
    int n0 = blockIdx.x * 32, k0 = blockIdx.y * 32;
#pragma unroll
    for (int i = 0; i < 4; i++) {
        int k = k0 + ty + i * 8, n = n0 + tx;
        tile[ty + i * 8][tx] = (k < Kin && n < Nin) ? W[(size_t)k * Nin + n] : 0.f;
    }
    __syncthreads();
#pragma unroll
    for (int i = 0; i < 4; i++) {
        int n = n0 + ty + i * 8, k = k0 + tx;
        if (n < Npad && k < Kin)
            T[(size_t)n * Kin + k] = __float2half_rn(tile[tx][ty + i * 8]);
    }
}

// ---------------- fp16 GEMM via mma.sync: C[M,Nc] = A[M,K] * B^T -------------
// A single fp16 (128-row M-tile); B single fp16 (NT-row N-tile).
// K-chunk 32, 3-stage cp.async, 1 MMA per tile. Row stride 80B.
template <int K, int NT>
__global__ void __launch_bounds__(256, 2) k_gemm_mma(const __half* __restrict__ A,
                                                     const __half* __restrict__ B,
                                                     float* __restrict__ C, int Nc) {
    constexpr int NS = K / 32;
    constexpr int A_TILE = 128 * 80;          // 10240
    constexpr int B_TILE = NT * 80;
    constexpr int STAGE = A_TILE + B_TILE;
    constexpr int WM = (NT == 128) ? 2 : 4;
    constexpr int WMS = 128 / WM;
    constexpr int MT = WMS / 16;
    extern __shared__ char smem[];
    const uint32_t sb = smem_u32(smem);
    const int tid = threadIdx.x;
    const int wid = tid >> 5, lane = tid & 31;
    const int warp_m = wid % WM, warp_n = wid / WM;
    const int row0 = blockIdx.y * 128;
    const int n0   = blockIdx.x * NT;

    const __half* srcA = A + (size_t)row0 * K;
    const __half* srcB = B + (size_t)n0 * K;

    auto load_stage = [&](int s) {
        uint32_t base = sb + (uint32_t)(s % 3) * STAGE;
        int k0 = s * 32;
#pragma unroll
        for (int it = 0; it < 2; it++) {              // A: 512 cp ops
            int idx = it * 256 + tid;
            int r = idx >> 2, cs = idx & 3;
            CP16(base + (uint32_t)(r * 80 + cs * 16),
                 srcA + (size_t)r * K + k0 + cs * 8);
        }
#pragma unroll
        for (int it = 0; it < NT / 64; it++) {        // B: NT*4 cp ops
            int idx = it * 256 + tid;
            int r = idx >> 2, cs = idx & 3;
            CP16(base + A_TILE + (uint32_t)(r * 80 + cs * 16),
                 srcB + (size_t)r * K + k0 + cs * 8);
        }
        CP_COMMIT();
    };

    load_stage(0);
    load_stage(1);

    float acc[MT][4][4];
#pragma unroll
    for (int i = 0; i < MT; i++)
#pragma unroll
        for (int j = 0; j < 4; j++)
#pragma unroll
            for (int q = 0; q < 4; q++) acc[i][j][q] = 0.f;

    const int a_r = (lane & 7) + ((lane >> 3) & 1) * 8;
    const int a_c = ((lane >> 4) & 1) * 8;
    const int b_n = (lane & 7) + ((lane >> 4) & 1) * 8;
    const int b_k = ((lane >> 3) & 1) * 8;

    for (int s = 0; s < NS; s++) {
        if (s < NS - 1) { CP_WAIT1(); } else { CP_WAIT0(); }
        __syncthreads();
        if (s + 2 < NS) load_stage(s + 2);
        uint32_t base = sb + (uint32_t)(s % 3) * STAGE;
#pragma unroll
        for (int kc = 0; kc < 2; kc++) {
            uint32_t bh[4][2];
#pragma unroll
            for (int pair = 0; pair < 2; pair++) {
                uint32_t boff = (uint32_t)(((warp_n * 32 + pair * 16 + b_n) * 40 + kc * 16 + b_k) * 2);
                uint32_t r0, r1, r2, r3;
                LDM4(r0, r1, r2, r3, base + A_TILE + boff);
                bh[pair * 2][0] = r0; bh[pair * 2][1] = r1;
                bh[pair * 2 + 1][0] = r2; bh[pair * 2 + 1][1] = r3;
            }
#pragma unroll
            for (int mt = 0; mt < MT; mt++) {
                uint32_t aoff = (uint32_t)(((warp_m * WMS + mt * 16 + a_r) * 40 + kc * 16 + a_c) * 2);
                uint32_t ah[4];
                LDM4(ah[0], ah[1], ah[2], ah[3], base + aoff);
#pragma unroll
                for (int nt = 0; nt < 4; nt++)
                    MMA16816(acc[mt][nt], ah, bh[nt]);
            }
        }
    }

    const int g = lane >> 2, tg = lane & 3;
#pragma unroll
    for (int mt = 0; mt < MT; mt++) {
#pragma unroll
        for (int nt = 0; nt < 4; nt++) {
            int col = n0 + warp_n * 32 + nt * 8 + tg * 2;
            if (col < Nc) {
                int r = row0 + warp_m * WMS + mt * 16 + g;
                *(float2*)&C[(size_t)r * Nc + col] = make_float2(acc[mt][nt][0], acc[mt][nt][1]);
                *(float2*)&C[(size_t)(r + 8) * Nc + col] = make_float2(acc[mt][nt][2], acc[mt][nt][3]);
            }
        }
    }
}

#define SMEM_G1 (3 * (10240 + 128 * 80))   // 61440
#define SMEM_G2 (3 * (10240 + 64 * 80))    // 46080

// ---------------- 3) depthwise conv (4 rows/block) + SiLU + RoPE + dt ---------
__global__ void __launch_bounds__(256) k_conv(const float* __restrict__ conv_w,
                                              const float* __restrict__ conv_b,
                                              const float* __restrict__ dt_bias) {
    const int row0 = blockIdx.x * 4;              // 4 consecutive rows, same batch
    const int l0 = row0 & (SEQ - 1);
    const int b = row0 >> 12;
    const int t = threadIdx.x;
    __shared__ float s[4][CONV_DIM];

    for (int ch = t; ch < CONV_DIM; ch += 256) {
        float w0 = conv_w[ch * 4 + 0], w1 = conv_w[ch * 4 + 1];
        float w2 = conv_w[ch * 4 + 2], w3 = conv_w[ch * 4 + 3];
        float bias = conv_b[ch];
        float z[7];
#pragma unroll
        for (int i = 0; i < 7; i++) {
            int ls = l0 + i - 3;
            z[i] = (ls >= 0) ? g_zx[(size_t)(b * SEQ + ls) * DPROJ + DI + ch] : 0.f;
        }
#pragma unroll
        for (int r = 0; r < 4; r++) {
            float acc = bias + z[r] * w0 + z[r + 1] * w1 + z[r + 2] * w2 + z[r + 3] * w3;
            s[r][ch] = siluf(acc);
        }
    }
    __syncthreads();

    // RoPE: 256 threads = 4 rows x 64 (which,j) slots
    {
        int r = t >> 6, tt = t & 63;
        int which = tt >> 5, j = tt & 31;
        int jb = DI + which * DS + j;
        float freq = powf(10000.f, -(float)j / 32.f);
        float ang = (float)(l0 + r) * freq;
        float sn, cs;
        sincosf(ang, &sn, &cs);
        float v1 = s[r][jb], v2 = s[r][jb + 32];
        float r1 = v1 * cs - v2 * sn;
        float r2 = v1 * sn + v2 * cs;
        __syncthreads();
        s[r][jb] = r1;
        s[r][jb + 32] = r2;
    }
    __syncthreads();

#pragma unroll
    for (int r = 0; r < 4; r++) {
        float* dst = g_xbc + (size_t)(row0 + r) * CONV_DIM;
        for (int ch = t; ch < CONV_DIM; ch += 256) dst[ch] = s[r][ch];
    }

    if (t < 4 * NH) {
        int r = t / NH, h = t % NH;
        float v = g_zx[(size_t)(row0 + r) * DPROJ + DT_OFF + h] + dt_bias[h];
        g_dt[(size_t)(row0 + r) * NH + h] = (v > 20.f) ? v : log1pf(expf(v));
    }
}

// ---------------- 3.5) head-invariant CB[i][j] = C_i . B_j per chunk ----------
__global__ void __launch_bounds__(256) k_cb() {
    const int cb = blockIdx.x;
    const int t = threadIdx.x;
    __shared__ float Bs[32][129];
    __shared__ float Cs[32][129];
    const int row0 = cb * CHK;

    for (int idx = t; idx < 32 * 128; idx += 256) {
        int i = idx >> 7, n = idx & 127;
        size_t g = (size_t)(row0 + i) * CONV_DIM;
        Bs[i][n] = g_xbc[g + DI + n];
        Cs[i][n] = g_xbc[g + DI + DS + n];
    }
    __syncthreads();

    int i = t >> 3, j0 = (t & 7) << 2;
    float s0 = 0, s1 = 0, s2 = 0, s3 = 0;
    for (int n = 0; n < 128; n++) {
        float cv = Cs[i][n];
        s0 += cv * Bs[j0 + 0][n];
        s1 += cv * Bs[j0 + 1][n];
        s2 += cv * Bs[j0 + 2][n];
        s3 += cv * Bs[j0 + 3][n];
    }
    float* dst = g_cb + (size_t)cb * (CHK * CHK) + i * CHK + j0;
    dst[0] = s0; dst[1] = s1; dst[2] = s2; dst[3] = s3;
}

// ---------------- 4) intra-chunk via tensor cores: Yd + states ----------------
__global__ void __launch_bounds__(256) k_chunk(const float* __restrict__ A_log) {
    const int h = blockIdx.x, c = blockIdx.y, b = blockIdx.z;
    __shared__ __half XTh[64][40];
    __shared__ __half XTl[64][40];
    __shared__ __half attf[32][40];
    __shared__ __half BcT[128][40];
    __shared__ float dts[32], dacs[32], coeff[32];
    const int t = threadIdx.x;
    const int wid = t >> 5, lane = t & 31;
    const int row0 = b * SEQ + c * CHK;
    const int cb = b * NC + c;

    for (int idx = t; idx < 32 * 64; idx += 256) {
        int i = idx >> 6, p = idx & 63;
        float v = g_xbc[(size_t)(row0 + i) * CONV_DIM + h * HD + p];
        split2(v, XTh[p][i], XTl[p][i]);
    }
    if (t < 32) dts[t] = g_dt[(size_t)(row0 + t) * NH + h];
    __syncthreads();
    if (t == 0) {
        float A = -expf(A_log[h]);
        float cs = 0.f;
        for (int i = 0; i < 32; i++) { cs += dts[i] * A; dacs[i] = cs; }
    }
    __syncthreads();
    if (t < 32) coeff[t] = dts[t] * expf(dacs[31] - dacs[t]);
    __syncthreads();

    {
        const float* cbp = g_cb + (size_t)cb * (CHK * CHK);
        for (int idx = t; idx < 1024; idx += 256) {
            int i = idx >> 5, j = idx & 31;
            float a = (j <= i) ? cbp[idx] * expf(dacs[i] - dacs[j]) * dts[j] : 0.f;
            attf[i][j] = __float2half_rn(a);
        }
    }
    for (int idx = t; idx < 32 * 128; idx += 256) {
        int l = idx >> 7, n = idx & 127;
        BcT[n][l] = __float2half_rn(g_xbc[(size_t)(row0 + l) * CONV_DIM + DI + n] * coeff[l]);
    }
    __syncthreads();

    const int a_r = (lane & 7) + ((lane >> 3) & 1) * 8;
    const int a_c = ((lane >> 4) & 1) * 8;
    const int b_n = (lane & 7) + ((lane >> 4) & 1) * 8;
    const int b_k = ((lane >> 3) & 1) * 8;
    const int g = lane >> 2, tg = lane & 3;
    const uint32_t xh = smem_u32(XTh), xl = smem_u32(XTl);
    const uint32_t atp = smem_u32(attf), bct = smem_u32(BcT);

    // --- Yd: 8 warps = (mw 0..1) x (nw 0..3 of 16 p) ---
    {
        const int mw = wid & 1, nw = wid >> 1;
        float acc0[4] = {0, 0, 0, 0}, acc1[4] = {0, 0, 0, 0};
#pragma unroll
        for (int k0 = 0; k0 < 32; k0 += 16) {
            uint32_t av[4], bh0[2], bh1[2], bl0[2], bl1[2];
            uint32_t aoff = (uint32_t)(((mw * 16 + a_r) * 40 + k0 + a_c) * 2);
            LDM4(av[0], av[1], av[2], av[3], atp + aoff);
            uint32_t boff = (uint32_t)(((nw * 16 + b_n) * 40 + k0 + b_k) * 2);
            uint32_t r0, r1, r2, r3;
            LDM4(r0, r1, r2, r3, xh + boff);
            bh0[0] = r0; bh0[1] = r1; bh1[0] = r2; bh1[1] = r3;
            LDM4(r0, r1, r2, r3, xl + boff);
            bl0[0] = r0; bl0[1] = r1; bl1[0] = r2; bl1[1] = r3;
            MMA16816(acc0, av, bh0);
            MMA16816(acc0, av, bl0);
            MMA16816(acc1, av, bh1);
            MMA16816(acc1, av, bl1);
        }
        int col0 = h * HD + nw * 16 + tg * 2;
        size_t r0 = (size_t)(row0 + mw * 16 + g) * DI;
        size_t r1 = (size_t)(row0 + mw * 16 + g + 8) * DI;
        *(float2*)&g_yv[r0 + col0]     = make_float2(acc0[0], acc0[1]);
        *(float2*)&g_yv[r1 + col0]     = make_float2(acc0[2], acc0[3]);
        *(float2*)&g_yv[r0 + col0 + 8] = make_float2(acc1[0], acc1[1]);
        *(float2*)&g_yv[r1 + col0 + 8] = make_float2(acc1[2], acc1[3]);
    }

    // --- states: 8 warps = (mw 0..3 of 16 p) x (nw 0..1 of 64 n) ---
    {
        const int mw = wid & 3, nw = wid >> 2;
        size_t sbase = ((size_t)((b * NC + c) * NH + h)) * (HD * DS);
#pragma unroll
        for (int ntile = 0; ntile < 4; ntile++) {
            float acc0[4] = {0, 0, 0, 0}, acc1[4] = {0, 0, 0, 0};
#pragma unroll
            for (int k0 = 0; k0 < 32; k0 += 16) {
                uint32_t ah[4], al[4], bb0[2], bb1[2];
                uint32_t aoff = (uint32_t)(((mw * 16 + a_r) * 40 + k0 + a_c) * 2);
                LDM4(ah[0], ah[1], ah[2], ah[3], xh + aoff);
                LDM4(al[0], al[1], al[2], al[3], xl + aoff);
                uint32_t boff = (uint32_t)(((nw * 64 + ntile * 16 + b_n) * 40 + k0 + b_k) * 2);
                uint32_t r0, r1, r2, r3;
                LDM4(r0, r1, r2, r3, bct + boff);
                bb0[0] = r0; bb0[1] = r1; bb1[0] = r2; bb1[1] = r3;
                MMA16816(acc0, ah, bb0);
                MMA16816(acc0, al, bb0);
                MMA16816(acc1, ah, bb1);
                MMA16816(acc1, al, bb1);
            }
            int p0 = mw * 16 + g;
            int n0 = nw * 64 + ntile * 16 + tg * 2;
            *(__half2*)&g_states[sbase + (size_t)p0 * DS + n0]           = __floats2half2_rn(acc0[0], acc0[1]);
            *(__half2*)&g_states[sbase + (size_t)(p0 + 8) * DS + n0]     = __floats2half2_rn(acc0[2], acc0[3]);
            *(__half2*)&g_states[sbase + (size_t)p0 * DS + n0 + 8]       = __floats2half2_rn(acc1[0], acc1[1]);
            *(__half2*)&g_states[sbase + (size_t)(p0 + 8) * DS + n0 + 8] = __floats2half2_rn(acc1[2], acc1[3]);
        }
    }
    if (t == 0) g_cd[(b * NC + c) * NH + h] = expf(dacs[31]);
}

// ---------------- 5) inter-chunk scan: states -> prev (fp16 storage) ----------
__global__ void __launch_bounds__(256) k_scan(const __half* __restrict__ st,
                                              __half* __restrict__ pv,
                                              const float* __restrict__ cd) {
    const int bh = blockIdx.x >> 3;
    const int j  = blockIdx.x & 7;
    const int b = bh / NH, h = bh % NH;
    const int elem = j * 1024 + threadIdx.x * 4;
    float s0 = 0.f, s1 = 0.f, s2 = 0.f, s3 = 0.f;
    for (int c = 0; c < NC; c++) {
        size_t base = ((size_t)((b * NC + c) * NH + h)) * (HD * DS) + elem;
        float cdv = cd[(b * NC + c) * NH + h];
        __half2 t01 = *(const __half2*)(st + base);
        __half2 t23 = *(const __half2*)(st + base + 2);
        __half2 p01 = __floats2half2_rn(s0, s1);
        __half2 p23 = __floats2half2_rn(s2, s3);
        *(__half2*)(pv + base) = p01;
        *(__half2*)(pv + base + 2) = p23;
        float2 f01 = __half22float2(t01);
        float2 f23 = __half22float2(t23);
        s0 = s0 * cdv + f01.x;
        s1 = s1 * cdv + f01.y;
        s2 = s2 * cdv + f23.x;
        s3 = s3 * cdv + f23.y;
    }
}

// ---------------- 6) Yo via tensor-core MMA + gate -> yv fp16 -----------------
__global__ void __launch_bounds__(256) k_yo(const float* __restrict__ A_log,
                                            const float* __restrict__ Dp) {
    const int h = blockIdx.x, c = blockIdx.y, b = blockIdx.z;
    __shared__ __half Cs_h[32][136];
    __shared__ __half Cs_l[32][136];
    __shared__ __half Pv[64][136];
    __shared__ float Yo_s[32][68];
    __shared__ float dts[32], dacs[32];
    const int t = threadIdx.x;
    const int wid = t >> 5, lane = t & 31;
    const int row0 = b * SEQ + c * CHK;

    for (int idx = t; idx < 32 * 128; idx += 256) {
        int i = idx >> 7, n = idx & 127;
        float v = g_xbc[(size_t)(row0 + i) * CONV_DIM + DI + DS + n];
        split2(v, Cs_h[i][n], Cs_l[i][n]);
    }
    {
        size_t pb = ((size_t)((b * NC + c) * NH + h)) * (HD * DS);
        const __half* src = g_prev + pb;
#pragma unroll
        for (int it = 0; it < 8; it++) {
            int idx = it * 256 + t;
            int p = idx >> 5, n0 = (idx & 31) * 4;
            *(uint2*)&Pv[p][n0] = *(const uint2*)(src + (size_t)p * DS + n0);
        }
    }
    if (t < 32) dts[t] = g_dt[(size_t)(row0 + t) * NH + h];
    __syncthreads();
    if (t == 0) {
        float A = -expf(A_log[h]);
        float cs = 0.f;
        for (int i = 0; i < 32; i++) { cs += dts[i] * A; dacs[i] = cs; }
    }

    {
        const int mw = wid & 1, nw = wid >> 1;
        const int a_r = (lane & 7) + ((lane >> 3) & 1) * 8;
        const int a_c = ((lane >> 4) & 1) * 8;
        const int b_n = (lane & 7) + ((lane >> 4) & 1) * 8;
        const int b_k = ((lane >> 3) & 1) * 8;
        float acc0[4] = {0, 0, 0, 0}, acc1[4] = {0, 0, 0, 0};
        const uint32_t csh = smem_u32(Cs_h);
        const uint32_t csl = smem_u32(Cs_l);
        const uint32_t pvb = smem_u32(Pv);
#pragma unroll
        for (int k0 = 0; k0 < 128; k0 += 16) {
            uint32_t ah[4], al[4], bb0[2], bb1[2];
            uint32_t aoff = (uint32_t)(((mw * 16 + a_r) * 136 + k0 + a_c) * 2);
            LDM4(ah[0], ah[1], ah[2], ah[3], csh + aoff);
            LDM4(al[0], al[1], al[2], al[3], csl + aoff);
            uint32_t boff = (uint32_t)(((nw * 16 + b_n) * 136 + k0 + b_k) * 2);
            uint32_t r0, r1, r2, r3;
            LDM4(r0, r1, r2, r3, pvb + boff);
            bb0[0] = r0; bb0[1] = r1; bb1[0] = r2; bb1[1] = r3;
            MMA16816(acc0, ah, bb0);
            MMA16816(acc0, al, bb0);
            MMA16816(acc1, ah, bb1);
            MMA16816(acc1, al, bb1);
        }
        int g = lane >> 2, tg = lane & 3;
        int pc0 = nw * 16 + tg * 2;
        Yo_s[mw * 16 + g][pc0]         = acc0[0];
        Yo_s[mw * 16 + g][pc0 + 1]     = acc0[1];
        Yo_s[mw * 16 + g + 8][pc0]     = acc0[2];
        Yo_s[mw * 16 + g + 8][pc0 + 1] = acc0[3];
        Yo_s[mw * 16 + g][pc0 + 8]         = acc1[0];
        Yo_s[mw * 16 + g][pc0 + 9]         = acc1[1];
        Yo_s[mw * 16 + g + 8][pc0 + 8]     = acc1[2];
        Yo_s[mw * 16 + g + 8][pc0 + 9]     = acc1[3];
    }
    __syncthreads();

    const int i = t >> 3, p0 = (t & 7) << 3;
    float ei = expf(dacs[i]);
    float dph = Dp[h];
    size_t row = row0 + i;
#pragma unroll
    for (int q = 0; q < 8; q++) {
        int p = p0 + q;
        float xin = g_xbc[row * CONV_DIM + h * HD + p];
        float z = g_zx[row * DPROJ + h * HD + p];
        size_t yi = row * DI + h * HD + p;
        float Y = g_yv[yi] + ei * Yo_s[i][p] + dph * xin;
        float outv = Y * siluf(z);
        g_yv_h[yi] = __float2half_rn(outv);
    }
}

// ---------------- 8) post-RMSNorm + residual ----------------
__global__ void __launch_bounds__(256) k_final(const float* __restrict__ x,
                                               const float* __restrict__ sc,
                                               float* __restrict__ out) {
    int row = blockIdx.x, t = threadIdx.x;
    const float* gr = g_out + (size_t)row * DM;
    float v0 = gr[t], v1 = gr[t + 256], v2 = gr[t + 512];
    float ss = block_reduce_sum(v0 * v0 + v1 * v1 + v2 * v2);
    float inv = rsqrtf(ss * (1.0f / DM) + EPS);
    const float* xr = x + (size_t)row * DM;
    size_t o = (size_t)row * DM;
    out[o + t]       = xr[t]       + v0 * inv * (1.f + sc[t]);
    out[o + t + 256] = xr[t + 256] + v1 * inv * (1.f + sc[t + 256]);
    out[o + t + 512] = xr[t + 512] + v2 * inv * (1.f + sc[t + 512]);
}

// ---------------- launch -----------------------------------------------------
extern "C" void kernel_launch(void* const* d_in, const int* in_sizes, int n_in,
                              void* d_out, int out_size) {
    const float* x          = (const float*)d_in[0];
    const float* pre_scale  = (const float*)d_in[1];
    const float* post_scale = (const float*)d_in[2];
    const float* W_in       = (const float*)d_in[3];
    const float* conv_w     = (const float*)d_in[4];
    const float* conv_b     = (const float*)d_in[5];
    const float* dt_bias    = (const float*)d_in[6];
    const float* A_log      = (const float*)d_in[7];
    const float* D_param    = (const float*)d_in[8];
    const float* W_out      = (const float*)d_in[9];
    float* out = (float*)d_out;

    static int configured = 0;
    if (!configured) {
        cudaFuncSetAttribute((const void*)k_gemm_mma<768, 128>,
                             cudaFuncAttributeMaxDynamicSharedMemorySize, SMEM_G1);
        cudaFuncSetAttribute((const void*)k_gemm_mma<1536, 64>,
                             cudaFuncAttributeMaxDynamicSharedMemorySize, SMEM_G2);
        configured = 1;
    }

    __half *yh, *winT, *woutT, *yvh, *stp, *pvp;
    float *zx, *outp, *cdp;
    cudaGetSymbolAddress((void**)&yh, g_y_h);
    cudaGetSymbolAddress((void**)&winT, g_winT);
    cudaGetSymbolAddress((void**)&woutT, g_woutT);
    cudaGetSymbolAddress((void**)&yvh, g_yv_h);
    cudaGetSymbolAddress((void**)&zx, g_zx);
    cudaGetSymbolAddress((void**)&outp, g_out);
    cudaGetSymbolAddress((void**)&stp, g_states);
    cudaGetSymbolAddress((void**)&pvp, g_prev);
    cudaGetSymbolAddress((void**)&cdp, g_cd);

    // launch index 3 == k_gemm_mma<768,128> (stable profiler reference)
    k_rms_pre<<<ROWS, 256>>>(x, pre_scale);
    k_wsplit<<<dim3(N1PAD / 32, DM / 32), 256>>>(W_in, winT, DM, DPROJ, N1PAD);
    k_wsplit<<<dim3(DM / 32, DI / 32), 256>>>(W_out, woutT, DI, DM, DM);
    k_gemm_mma<768, 128><<<dim3(N1PAD / 128, ROWS / 128), 256, SMEM_G1>>>(yh, winT, zx, DPROJ);
    k_conv<<<ROWS / 4, 256>>>(conv_w, conv_b, dt_bias);
    k_cb<<<BATCH * NC, 256>>>();
    k_chunk<<<dim3(NH, NC, BATCH), 256>>>(A_log);
    k_scan<<<BATCH * NH * 8, 256>>>(stp, pvp, cdp);
    k_yo<<<dim3(NH, NC, BATCH), 256>>>(A_log, D_param);
    k_gemm_mma<1536, 64><<<dim3(DM / 64, ROWS / 128), 256, SMEM_G2>>>(yvh, woutT, outp, DM);
    k_final<<<ROWS, 256>>>(x, post_scale, out);
}